// round 1
// baseline (speedup 1.0000x reference)
#include <cuda_runtime.h>
#include <math.h>

// ---------------------------------------------------------------------------
// Problem constants
// ---------------------------------------------------------------------------
#define NB      2
#define T_SEQ   2048
#define NT      (NB * T_SEQ)        // 4096 tokens
#define DM      1024                // d_model
#define H_NUM   16
#define HD      64                  // head dim
#define DFF     4096
#define QKV_N   (3 * DM)            // 3072
#define LN_EPS  1e-3f

// ---------------------------------------------------------------------------
// Scratch (static device memory; allocation is forbidden)
// ---------------------------------------------------------------------------
__device__ float g_qkv[NT * QKV_N];     // 50 MB
__device__ float g_ctx[NT * DM];        // 16 MB
__device__ float g_h1 [NT * DM];        // 16 MB
__device__ float g_ff [NT * DFF];       // 67 MB
__device__ float g_tmp[NT * DM];        // 16 MB

// ---------------------------------------------------------------------------
// Generic tiled GEMM:  C[M,N] = A[M,K] @ B[K,N] + bias[N]   (optional ReLU)
// BM=BN=64, BK=16, 256 threads, 4x4 microtile per thread.
// ---------------------------------------------------------------------------
__global__ void gemm_bias_kernel(const float* __restrict__ A,
                                 const float* __restrict__ B,
                                 const float* __restrict__ bias,
                                 float* __restrict__ C,
                                 int M, int N, int K, int relu)
{
    __shared__ float As[16][65];   // transposed A tile, padded
    __shared__ float Bs[16][64];

    const int tid = threadIdx.x;
    const int tx  = tid & 15;
    const int ty  = tid >> 4;
    const int m0  = blockIdx.y * 64;
    const int n0  = blockIdx.x * 64;

    float acc[4][4] = {};

    for (int k0 = 0; k0 < K; k0 += 16) {
        // Load A tile (64 x 16) -> As[k][m]
        #pragma unroll
        for (int idx = tid; idx < 64 * 16; idx += 256) {
            int m = idx >> 4, k = idx & 15;
            As[k][m] = A[(size_t)(m0 + m) * K + (k0 + k)];
        }
        // Load B tile (16 x 64) -> Bs[k][n]
        #pragma unroll
        for (int idx = tid; idx < 16 * 64; idx += 256) {
            int k = idx >> 6, n = idx & 63;
            Bs[k][n] = B[(size_t)(k0 + k) * N + (n0 + n)];
        }
        __syncthreads();

        #pragma unroll
        for (int kk = 0; kk < 16; kk++) {
            float a[4], b[4];
            #pragma unroll
            for (int i = 0; i < 4; i++) a[i] = As[kk][ty * 4 + i];
            #pragma unroll
            for (int j = 0; j < 4; j++) b[j] = Bs[kk][tx * 4 + j];
            #pragma unroll
            for (int i = 0; i < 4; i++)
                #pragma unroll
                for (int j = 0; j < 4; j++)
                    acc[i][j] = fmaf(a[i], b[j], acc[i][j]);
        }
        __syncthreads();
    }

    #pragma unroll
    for (int i = 0; i < 4; i++) {
        int m = m0 + ty * 4 + i;
        #pragma unroll
        for (int j = 0; j < 4; j++) {
            int n = n0 + tx * 4 + j;
            float v = acc[i][j] + bias[n];
            if (relu) v = fmaxf(v, 0.0f);
            C[(size_t)m * N + n] = v;
        }
    }
}

// ---------------------------------------------------------------------------
// Flash-attention style kernel.
// Grid: (T/64, H, N).  Block: 256 threads.
// qkv layout per token row (len 3072): element ((h*64+d)*3 + c), c in {q,k,v}.
// Mask hits the QUERY axis in the reference -> per-row constant shift into
// softmax -> no effect on the output. Skipped.
// ---------------------------------------------------------------------------
__global__ void attention_kernel(const float* __restrict__ qkv,
                                 float* __restrict__ ctx)
{
    __shared__ float Qs[64][65];
    __shared__ float Ks[32][65];
    __shared__ float Vs[32][64];
    __shared__ float Ss[64][33];
    __shared__ float m_s[64], l_s[64], a_s[64];

    const int tid = threadIdx.x;
    const int tx  = tid & 15;
    const int ty  = tid >> 4;
    const int q0  = blockIdx.x * 64;
    const int h   = blockIdx.y;
    const int n   = blockIdx.z;

    const size_t row_base = (size_t)n * T_SEQ;

    // Load Q tile (64 x 64)
    for (int idx = tid; idx < 64 * 64; idx += 256) {
        int r = idx >> 6, d = idx & 63;
        Qs[r][d] = qkv[(row_base + q0 + r) * QKV_N + (h * HD + d) * 3 + 0];
    }
    if (tid < 64) { m_s[tid] = -1e30f; l_s[tid] = 0.0f; }

    float acc[4][4] = {};

    for (int kt = 0; kt < T_SEQ / 32; kt++) {
        const int kv0 = kt * 32;
        __syncthreads();
        // Load K,V tiles (32 x 64)
        for (int idx = tid; idx < 32 * 64; idx += 256) {
            int r = idx >> 6, d = idx & 63;
            size_t base = (row_base + kv0 + r) * (size_t)QKV_N + (h * HD + d) * 3;
            Ks[r][d] = qkv[base + 1];
            Vs[r][d] = qkv[base + 2];
        }
        __syncthreads();

        // S = (Q @ K^T) * scale  : each thread 4 rows x 2 cols
        #pragma unroll
        for (int i = 0; i < 4; i++) {
            int r = ty * 4 + i;
            #pragma unroll
            for (int j = 0; j < 2; j++) {
                int c = tx * 2 + j;
                float s = 0.0f;
                #pragma unroll 8
                for (int kk = 0; kk < 64; kk++)
                    s = fmaf(Qs[r][kk], Ks[c][kk], s);
                Ss[r][c] = s * 0.125f;
            }
        }
        __syncthreads();

        // Online softmax bookkeeping (64 threads, one row each)
        if (tid < 64) {
            float mold = m_s[tid];
            float mt = mold;
            #pragma unroll
            for (int k = 0; k < 32; k++) mt = fmaxf(mt, Ss[tid][k]);
            float al = __expf(mold - mt);
            float ls = 0.0f;
            #pragma unroll
            for (int k = 0; k < 32; k++) {
                float p = __expf(Ss[tid][k] - mt);
                Ss[tid][k] = p;
                ls += p;
            }
            m_s[tid] = mt;
            l_s[tid] = l_s[tid] * al + ls;
            a_s[tid] = al;
        }
        __syncthreads();

        // Rescale accumulators + accumulate P @ V  (4 rows x 4 dims)
        #pragma unroll
        for (int i = 0; i < 4; i++) {
            int r = ty * 4 + i;
            float al = a_s[r];
            #pragma unroll
            for (int j = 0; j < 4; j++) acc[i][j] *= al;
            #pragma unroll 8
            for (int k = 0; k < 32; k++) {
                float p = Ss[r][k];
                #pragma unroll
                for (int j = 0; j < 4; j++)
                    acc[i][j] = fmaf(p, Vs[k][tx * 4 + j], acc[i][j]);
            }
        }
    }
    __syncthreads();

    // Write ctx[n, t, h*64+d] = acc / l
    #pragma unroll
    for (int i = 0; i < 4; i++) {
        int r = ty * 4 + i;
        float inv_l = 1.0f / l_s[r];
        #pragma unroll
        for (int j = 0; j < 4; j++) {
            int d = tx * 4 + j;
            ctx[(row_base + q0 + r) * (size_t)DM + h * HD + d] = acc[i][j] * inv_l;
        }
    }
}

// ---------------------------------------------------------------------------
// out[row] = LayerNorm(a[row] + b[row]) * gamma + beta   (D = 1024)
// One block per row, 256 threads, 4 elements each.
// ---------------------------------------------------------------------------
__global__ void add_ln_kernel(const float* __restrict__ a,
                              const float* __restrict__ b,
                              const float* __restrict__ gamma,
                              const float* __restrict__ beta,
                              float* __restrict__ out)
{
    __shared__ float red[256];
    const int row = blockIdx.x;
    const int tid = threadIdx.x;
    const size_t base = (size_t)row * DM;

    float v[4];
    float s = 0.0f;
    #pragma unroll
    for (int i = 0; i < 4; i++) {
        int c = tid + 256 * i;
        v[i] = a[base + c] + b[base + c];
        s += v[i];
    }
    red[tid] = s;
    __syncthreads();
    #pragma unroll
    for (int off = 128; off > 0; off >>= 1) {
        if (tid < off) red[tid] += red[tid + off];
        __syncthreads();
    }
    const float mu = red[0] * (1.0f / DM);
    __syncthreads();

    float s2 = 0.0f;
    #pragma unroll
    for (int i = 0; i < 4; i++) {
        float d = v[i] - mu;
        s2 += d * d;
    }
    red[tid] = s2;
    __syncthreads();
    #pragma unroll
    for (int off = 128; off > 0; off >>= 1) {
        if (tid < off) red[tid] += red[tid + off];
        __syncthreads();
    }
    const float rs = rsqrtf(red[0] * (1.0f / DM) + LN_EPS);

    #pragma unroll
    for (int i = 0; i < 4; i++) {
        int c = tid + 256 * i;
        out[base + c] = (v[i] - mu) * rs * gamma[c] + beta[c];
    }
}

// ---------------------------------------------------------------------------
// Launch
// ---------------------------------------------------------------------------
extern "C" void kernel_launch(void* const* d_in, const int* in_sizes, int n_in,
                              void* d_out, int out_size)
{
    const float* x     = (const float*)d_in[0];
    /* mask = d_in[1] : no effect on output (query-axis mask -> softmax shift) */
    const float* w_qkv = (const float*)d_in[2];
    const float* b_qkv = (const float*)d_in[3];
    const float* w_ff  = (const float*)d_in[4];
    const float* b_ff  = (const float*)d_in[5];
    const float* w_out = (const float*)d_in[6];
    const float* b_out = (const float*)d_in[7];
    const float* ln1_g = (const float*)d_in[8];
    const float* ln1_b = (const float*)d_in[9];
    const float* ln2_g = (const float*)d_in[10];
    const float* ln2_b = (const float*)d_in[11];
    float* out = (float*)d_out;

    float *qkv, *ctx, *h1, *ff, *tmp;
    cudaGetSymbolAddress((void**)&qkv, g_qkv);
    cudaGetSymbolAddress((void**)&ctx, g_ctx);
    cudaGetSymbolAddress((void**)&h1,  g_h1);
    cudaGetSymbolAddress((void**)&ff,  g_ff);
    cudaGetSymbolAddress((void**)&tmp, g_tmp);

    // 1) QKV projection: [4096,1024] @ [1024,3072]
    gemm_bias_kernel<<<dim3(QKV_N / 64, NT / 64), 256>>>(
        x, w_qkv, b_qkv, qkv, NT, QKV_N, DM, 0);

    // 2) Attention
    attention_kernel<<<dim3(T_SEQ / 64, H_NUM, NB), 256>>>(qkv, ctx);

    // 3) h1 = LN(x + ctx)
    add_ln_kernel<<<NT, 256>>>(x, ctx, ln1_g, ln1_b, h1);

    // 4) ff = relu(h1 @ w_ff + b_ff): [4096,1024] @ [1024,4096]
    gemm_bias_kernel<<<dim3(DFF / 64, NT / 64), 256>>>(
        h1, w_ff, b_ff, ff, NT, DFF, DM, 1);

    // 5) tmp = ff @ w_out + b_out: [4096,4096] @ [4096,1024]
    gemm_bias_kernel<<<dim3(DM / 64, NT / 64), 256>>>(
        ff, w_out, b_out, tmp, NT, DM, DFF, 0);

    // 6) out = LN(h1 + tmp)
    add_ln_kernel<<<NT, 256>>>(h1, tmp, ln2_g, ln2_b, out);
}

// round 2
// speedup vs baseline: 1.3507x; 1.3507x over previous
#include <cuda_runtime.h>
#include <cuda_bf16.h>
#include <math.h>
#include <stdint.h>

// ---------------------------------------------------------------------------
// Problem constants
// ---------------------------------------------------------------------------
#define NB      2
#define T_SEQ   2048
#define NT      (NB * T_SEQ)        // 4096 tokens
#define DM      1024                // d_model
#define H_NUM   16
#define HD      64                  // head dim
#define DFF     4096
#define QKV_N   (3 * DM)            // 3072
#define LN_EPS  1e-3f

// ---------------------------------------------------------------------------
// Scratch (static device memory; allocation is forbidden)
// ---------------------------------------------------------------------------
__device__ float g_qkv[NT * QKV_N];     // 50 MB
__device__ float g_ctx[NT * DM];        // 16 MB
__device__ float g_h1 [NT * DM];        // 16 MB
__device__ float g_ff [NT * DFF];       // 67 MB
__device__ float g_tmp[NT * DM];        // 16 MB

// ---------------------------------------------------------------------------
// bf16x3 split helpers: a = hi + lo, each bf16. Packs (even,odd) k-pair into
// one uint32 with the even element in the low 16 bits (mma fragment order).
// ---------------------------------------------------------------------------
__device__ __forceinline__ void split_pack2(float x, float y,
                                            uint32_t& hi, uint32_t& lo)
{
    __nv_bfloat16 hx = __float2bfloat16(x);
    __nv_bfloat16 hy = __float2bfloat16(y);
    __nv_bfloat16 lx = __float2bfloat16(x - __bfloat162float(hx));
    __nv_bfloat16 ly = __float2bfloat16(y - __bfloat162float(hy));
    hi = (uint32_t)__bfloat16_as_ushort(hx) |
         ((uint32_t)__bfloat16_as_ushort(hy) << 16);
    lo = (uint32_t)__bfloat16_as_ushort(lx) |
         ((uint32_t)__bfloat16_as_ushort(ly) << 16);
}

#define MMA_BF16(d, a, b)                                                   \
    asm volatile(                                                           \
        "mma.sync.aligned.m16n8k16.row.col.f32.bf16.bf16.f32 "              \
        "{%0,%1,%2,%3}, {%4,%5,%6,%7}, {%8,%9}, {%0,%1,%2,%3};"             \
        : "+f"(d[0]), "+f"(d[1]), "+f"(d[2]), "+f"(d[3])                    \
        : "r"(a[0]), "r"(a[1]), "r"(a[2]), "r"(a[3]), "r"(b[0]), "r"(b[1]))

// ---------------------------------------------------------------------------
// Tensor-core GEMM (bf16x3 split, fp32-grade accuracy):
//   C[M,N] = A[M,K] @ B[K,N] + bias[N]   (optional ReLU)
// Block tile 128x128x32, 256 threads = 8 warps (4x2), warp tile 32x64,
// mma.sync m16n8k16 (2 m-tiles x 8 n-tiles per warp).
// Requires M%128==0, N%128==0, K%32==0 (true for all three GEMMs here).
// ---------------------------------------------------------------------------
__global__ __launch_bounds__(256, 1)
void gemm_mma_kernel(const float* __restrict__ A,
                     const float* __restrict__ B,
                     const float* __restrict__ bias,
                     float* __restrict__ C,
                     int M, int N, int K, int relu)
{
    // bf16x2-packed tiles; row stride 17 uint32 for bank spread.
    __shared__ uint32_t Ah[128][17], Al[128][17];
    __shared__ uint32_t Bh[128][17], Bl[128][17];

    const int tid  = threadIdx.x;
    const int warp = tid >> 5;
    const int lane = tid & 31;
    const int m0   = blockIdx.y * 128;
    const int n0   = blockIdx.x * 128;
    const int wm   = (warp >> 1) * 32;   // warp row offset in block tile
    const int wn   = (warp & 1) * 64;    // warp col offset in block tile
    const int tg   = lane & 3;           // thread-in-group
    const int grp  = lane >> 2;          // group id (0..7)

    float acc[2][8][4];
    #pragma unroll
    for (int i = 0; i < 2; i++)
        #pragma unroll
        for (int j = 0; j < 8; j++)
            #pragma unroll
            for (int q = 0; q < 4; q++) acc[i][j][q] = 0.0f;

    for (int k0 = 0; k0 < K; k0 += 32) {
        // ---- Load A tile (128 x 32 fp32), split+pack into smem ----
        #pragma unroll
        for (int t = 0; t < 4; t++) {
            int idx = tid + t * 256;            // 0..1023
            int m   = idx >> 3;                 // 0..127
            int k4  = (idx & 7) * 4;            // 0..28
            float4 v = *(const float4*)&A[(size_t)(m0 + m) * K + k0 + k4];
            uint32_t h0, l0, h1, l1;
            split_pack2(v.x, v.y, h0, l0);
            split_pack2(v.z, v.w, h1, l1);
            Ah[m][k4 / 2]     = h0;  Al[m][k4 / 2]     = l0;
            Ah[m][k4 / 2 + 1] = h1;  Al[m][k4 / 2 + 1] = l1;
        }
        // ---- Load B tile (32 x 128 fp32), transpose+split+pack ----
        #pragma unroll
        for (int t = 0; t < 2; t++) {
            int idx = tid + t * 256;            // 0..511
            int kp  = idx >> 5;                 // k-pair index 0..15
            int n4  = (idx & 31) * 4;           // 0..124
            const float* Brow = &B[(size_t)(k0 + 2 * kp) * N + n0 + n4];
            float4 u = *(const float4*)Brow;        // even k row
            float4 w = *(const float4*)(Brow + N);  // odd  k row
            uint32_t h, l;
            split_pack2(u.x, w.x, h, l); Bh[n4 + 0][kp] = h; Bl[n4 + 0][kp] = l;
            split_pack2(u.y, w.y, h, l); Bh[n4 + 1][kp] = h; Bl[n4 + 1][kp] = l;
            split_pack2(u.z, w.z, h, l); Bh[n4 + 2][kp] = h; Bl[n4 + 2][kp] = l;
            split_pack2(u.w, w.w, h, l); Bh[n4 + 3][kp] = h; Bl[n4 + 3][kp] = l;
        }
        __syncthreads();

        // ---- Compute: two k16 chunks ----
        #pragma unroll
        for (int kc = 0; kc < 2; kc++) {
            const int c8 = kc * 8;
            uint32_t afh[2][4], afl[2][4], bfh[8][2], bfl[8][2];
            #pragma unroll
            for (int i = 0; i < 2; i++) {
                int r = wm + i * 16 + grp;
                afh[i][0] = Ah[r][c8 + tg];
                afh[i][1] = Ah[r + 8][c8 + tg];
                afh[i][2] = Ah[r][c8 + 4 + tg];
                afh[i][3] = Ah[r + 8][c8 + 4 + tg];
                afl[i][0] = Al[r][c8 + tg];
                afl[i][1] = Al[r + 8][c8 + tg];
                afl[i][2] = Al[r][c8 + 4 + tg];
                afl[i][3] = Al[r + 8][c8 + 4 + tg];
            }
            #pragma unroll
            for (int j = 0; j < 8; j++) {
                int n = wn + j * 8 + grp;
                bfh[j][0] = Bh[n][c8 + tg];
                bfh[j][1] = Bh[n][c8 + 4 + tg];
                bfl[j][0] = Bl[n][c8 + tg];
                bfl[j][1] = Bl[n][c8 + 4 + tg];
            }
            #pragma unroll
            for (int i = 0; i < 2; i++)
                #pragma unroll
                for (int j = 0; j < 8; j++) {
                    MMA_BF16(acc[i][j], afh[i], bfh[j]);   // hi*hi
                    MMA_BF16(acc[i][j], afh[i], bfl[j]);   // hi*lo
                    MMA_BF16(acc[i][j], afl[i], bfh[j]);   // lo*hi
                }
        }
        __syncthreads();
    }

    // ---- Epilogue: bias (+ReLU), float2 stores ----
    #pragma unroll
    for (int i = 0; i < 2; i++) {
        int r = m0 + wm + i * 16 + grp;
        #pragma unroll
        for (int j = 0; j < 8; j++) {
            int c = n0 + wn + j * 8 + tg * 2;
            float b0 = bias[c], b1 = bias[c + 1];
            float2 v0 = make_float2(acc[i][j][0] + b0, acc[i][j][1] + b1);
            float2 v1 = make_float2(acc[i][j][2] + b0, acc[i][j][3] + b1);
            if (relu) {
                v0.x = fmaxf(v0.x, 0.0f); v0.y = fmaxf(v0.y, 0.0f);
                v1.x = fmaxf(v1.x, 0.0f); v1.y = fmaxf(v1.y, 0.0f);
            }
            *(float2*)&C[(size_t)r * N + c]       = v0;
            *(float2*)&C[(size_t)(r + 8) * N + c] = v1;
        }
    }
}

// ---------------------------------------------------------------------------
// Flash-attention style kernel (fp32, unchanged from R0).
// Grid: (T/64, H, N).  Block: 256 threads.
// qkv layout per token row (len 3072): element ((h*64+d)*3 + c), c in {q,k,v}.
// Mask hits the QUERY axis in the reference -> per-row constant shift into
// softmax -> no effect on the output. Skipped.
// ---------------------------------------------------------------------------
__global__ void attention_kernel(const float* __restrict__ qkv,
                                 float* __restrict__ ctx)
{
    __shared__ float Qs[64][65];
    __shared__ float Ks[32][65];
    __shared__ float Vs[32][64];
    __shared__ float Ss[64][33];
    __shared__ float m_s[64], l_s[64], a_s[64];

    const int tid = threadIdx.x;
    const int tx  = tid & 15;
    const int ty  = tid >> 4;
    const int q0  = blockIdx.x * 64;
    const int h   = blockIdx.y;
    const int n   = blockIdx.z;

    const size_t row_base = (size_t)n * T_SEQ;

    for (int idx = tid; idx < 64 * 64; idx += 256) {
        int r = idx >> 6, d = idx & 63;
        Qs[r][d] = qkv[(row_base + q0 + r) * QKV_N + (h * HD + d) * 3 + 0];
    }
    if (tid < 64) { m_s[tid] = -1e30f; l_s[tid] = 0.0f; }

    float acc[4][4] = {};

    for (int kt = 0; kt < T_SEQ / 32; kt++) {
        const int kv0 = kt * 32;
        __syncthreads();
        for (int idx = tid; idx < 32 * 64; idx += 256) {
            int r = idx >> 6, d = idx & 63;
            size_t base = (row_base + kv0 + r) * (size_t)QKV_N + (h * HD + d) * 3;
            Ks[r][d] = qkv[base + 1];
            Vs[r][d] = qkv[base + 2];
        }
        __syncthreads();

        #pragma unroll
        for (int i = 0; i < 4; i++) {
            int r = ty * 4 + i;
            #pragma unroll
            for (int j = 0; j < 2; j++) {
                int c = tx * 2 + j;
                float s = 0.0f;
                #pragma unroll 8
                for (int kk = 0; kk < 64; kk++)
                    s = fmaf(Qs[r][kk], Ks[c][kk], s);
                Ss[r][c] = s * 0.125f;
            }
        }
        __syncthreads();

        if (tid < 64) {
            float mold = m_s[tid];
            float mt = mold;
            #pragma unroll
            for (int k = 0; k < 32; k++) mt = fmaxf(mt, Ss[tid][k]);
            float al = __expf(mold - mt);
            float ls = 0.0f;
            #pragma unroll
            for (int k = 0; k < 32; k++) {
                float p = __expf(Ss[tid][k] - mt);
                Ss[tid][k] = p;
                ls += p;
            }
            m_s[tid] = mt;
            l_s[tid] = l_s[tid] * al + ls;
            a_s[tid] = al;
        }
        __syncthreads();

        #pragma unroll
        for (int i = 0; i < 4; i++) {
            int r = ty * 4 + i;
            float al = a_s[r];
            #pragma unroll
            for (int j = 0; j < 4; j++) acc[i][j] *= al;
            #pragma unroll 8
            for (int k = 0; k < 32; k++) {
                float p = Ss[r][k];
                #pragma unroll
                for (int j = 0; j < 4; j++)
                    acc[i][j] = fmaf(p, Vs[k][tx * 4 + j], acc[i][j]);
            }
        }
    }
    __syncthreads();

    #pragma unroll
    for (int i = 0; i < 4; i++) {
        int r = ty * 4 + i;
        float inv_l = 1.0f / l_s[r];
        #pragma unroll
        for (int j = 0; j < 4; j++) {
            int d = tx * 4 + j;
            ctx[(row_base + q0 + r) * (size_t)DM + h * HD + d] = acc[i][j] * inv_l;
        }
    }
}

// ---------------------------------------------------------------------------
// out[row] = LayerNorm(a[row] + b[row]) * gamma + beta   (D = 1024)
// ---------------------------------------------------------------------------
__global__ void add_ln_kernel(const float* __restrict__ a,
                              const float* __restrict__ b,
                              const float* __restrict__ gamma,
                              const float* __restrict__ beta,
                              float* __restrict__ out)
{
    __shared__ float red[256];
    const int row = blockIdx.x;
    const int tid = threadIdx.x;
    const size_t base = (size_t)row * DM;

    float v[4];
    float s = 0.0f;
    #pragma unroll
    for (int i = 0; i < 4; i++) {
        int c = tid + 256 * i;
        v[i] = a[base + c] + b[base + c];
        s += v[i];
    }
    red[tid] = s;
    __syncthreads();
    #pragma unroll
    for (int off = 128; off > 0; off >>= 1) {
        if (tid < off) red[tid] += red[tid + off];
        __syncthreads();
    }
    const float mu = red[0] * (1.0f / DM);
    __syncthreads();

    float s2 = 0.0f;
    #pragma unroll
    for (int i = 0; i < 4; i++) {
        float d = v[i] - mu;
        s2 += d * d;
    }
    red[tid] = s2;
    __syncthreads();
    #pragma unroll
    for (int off = 128; off > 0; off >>= 1) {
        if (tid < off) red[tid] += red[tid + off];
        __syncthreads();
    }
    const float rs = rsqrtf(red[0] * (1.0f / DM) + LN_EPS);

    #pragma unroll
    for (int i = 0; i < 4; i++) {
        int c = tid + 256 * i;
        out[base + c] = (v[i] - mu) * rs * gamma[c] + beta[c];
    }
}

// ---------------------------------------------------------------------------
// Launch
// ---------------------------------------------------------------------------
extern "C" void kernel_launch(void* const* d_in, const int* in_sizes, int n_in,
                              void* d_out, int out_size)
{
    const float* x     = (const float*)d_in[0];
    /* mask = d_in[1] : no effect on output (query-axis mask -> softmax shift) */
    const float* w_qkv = (const float*)d_in[2];
    const float* b_qkv = (const float*)d_in[3];
    const float* w_ff  = (const float*)d_in[4];
    const float* b_ff  = (const float*)d_in[5];
    const float* w_out = (const float*)d_in[6];
    const float* b_out = (const float*)d_in[7];
    const float* ln1_g = (const float*)d_in[8];
    const float* ln1_b = (const float*)d_in[9];
    const float* ln2_g = (const float*)d_in[10];
    const float* ln2_b = (const float*)d_in[11];
    float* out = (float*)d_out;

    float *qkv, *ctx, *h1, *ff, *tmp;
    cudaGetSymbolAddress((void**)&qkv, g_qkv);
    cudaGetSymbolAddress((void**)&ctx, g_ctx);
    cudaGetSymbolAddress((void**)&h1,  g_h1);
    cudaGetSymbolAddress((void**)&ff,  g_ff);
    cudaGetSymbolAddress((void**)&tmp, g_tmp);

    // 1) QKV projection: [4096,1024] @ [1024,3072]
    gemm_mma_kernel<<<dim3(QKV_N / 128, NT / 128), 256>>>(
        x, w_qkv, b_qkv, qkv, NT, QKV_N, DM, 0);

    // 2) Attention
    attention_kernel<<<dim3(T_SEQ / 64, H_NUM, NB), 256>>>(qkv, ctx);

    // 3) h1 = LN(x + ctx)
    add_ln_kernel<<<NT, 256>>>(x, ctx, ln1_g, ln1_b, h1);

    // 4) ff = relu(h1 @ w_ff + b_ff): [4096,1024] @ [1024,4096]
    gemm_mma_kernel<<<dim3(DFF / 128, NT / 128), 256>>>(
        h1, w_ff, b_ff, ff, NT, DFF, DM, 1);

    // 5) tmp = ff @ w_out + b_out: [4096,4096] @ [4096,1024]
    gemm_mma_kernel<<<dim3(DM / 128, NT / 128), 256>>>(
        ff, w_out, b_out, tmp, NT, DM, DFF, 0);

    // 6) out = LN(h1 + tmp)
    add_ln_kernel<<<NT, 256>>>(h1, tmp, ln2_g, ln2_b, out);
}

// round 3
// speedup vs baseline: 3.0857x; 2.2845x over previous
#include <cuda_runtime.h>
#include <cuda_bf16.h>
#include <math.h>
#include <stdint.h>

// ---------------------------------------------------------------------------
// Problem constants
// ---------------------------------------------------------------------------
#define NB      2
#define T_SEQ   2048
#define NT      (NB * T_SEQ)        // 4096 tokens
#define DM      1024
#define H_NUM   16
#define HD      64
#define DFF     4096
#define QKV_N   (3 * DM)            // 3072
#define LN_EPS  1e-3f

// ---------------------------------------------------------------------------
// Scratch
// ---------------------------------------------------------------------------
__device__ float g_qkv[NT * QKV_N];
__device__ float g_ctx[NT * DM];
__device__ float g_h1 [NT * DM];
__device__ float g_ff [NT * DFF];
__device__ float g_tmp[NT * DM];

// ---------------------------------------------------------------------------
// bf16 split/pack helpers
// ---------------------------------------------------------------------------
__device__ __forceinline__ void split_pack2(float x, float y,
                                            uint32_t& hi, uint32_t& lo)
{
    __nv_bfloat16 hx = __float2bfloat16(x);
    __nv_bfloat16 hy = __float2bfloat16(y);
    __nv_bfloat16 lx = __float2bfloat16(x - __bfloat162float(hx));
    __nv_bfloat16 ly = __float2bfloat16(y - __bfloat162float(hy));
    hi = (uint32_t)__bfloat16_as_ushort(hx) |
         ((uint32_t)__bfloat16_as_ushort(hy) << 16);
    lo = (uint32_t)__bfloat16_as_ushort(lx) |
         ((uint32_t)__bfloat16_as_ushort(ly) << 16);
}

__device__ __forceinline__ uint32_t pack_bf16(float x, float y)
{
    return (uint32_t)__bfloat16_as_ushort(__float2bfloat16(x)) |
           ((uint32_t)__bfloat16_as_ushort(__float2bfloat16(y)) << 16);
}

#define MMA_BF16(d, a, b)                                                   \
    asm volatile(                                                           \
        "mma.sync.aligned.m16n8k16.row.col.f32.bf16.bf16.f32 "              \
        "{%0,%1,%2,%3}, {%4,%5,%6,%7}, {%8,%9}, {%0,%1,%2,%3};"             \
        : "+f"(d[0]), "+f"(d[1]), "+f"(d[2]), "+f"(d[3])                    \
        : "r"(a[0]), "r"(a[1]), "r"(a[2]), "r"(a[3]), "r"(b[0]), "r"(b[1]))

// ---------------------------------------------------------------------------
// Tensor-core GEMM (bf16x3 split), DOUBLE-BUFFERED.
// C[M,N] = A[M,K] @ B[K,N] + bias[N] (optional ReLU)
// Block tile 128x128x32, 256 threads (8 warps 4x2), warp 32x64.
// Dynamic smem: 4 arrays x [2][128][17] u32 = 69632 B.
// ---------------------------------------------------------------------------
#define SBUF 2176   // 128*17
#define AH_(b,r,k) dynsmem[          (b)*SBUF + (r)*17 + (k)]
#define AL_(b,r,k) dynsmem[2*SBUF +  (b)*SBUF + (r)*17 + (k)]
#define BH_(b,r,k) dynsmem[4*SBUF +  (b)*SBUF + (r)*17 + (k)]
#define BL_(b,r,k) dynsmem[6*SBUF +  (b)*SBUF + (r)*17 + (k)]
#define GEMM_SMEM_BYTES (8 * SBUF * 4)

__global__ __launch_bounds__(256)
void gemm_mma_kernel(const float* __restrict__ A,
                     const float* __restrict__ B,
                     const float* __restrict__ bias,
                     float* __restrict__ C,
                     int M, int N, int K, int relu)
{
    extern __shared__ uint32_t dynsmem[];

    const int tid  = threadIdx.x;
    const int warp = tid >> 5;
    const int lane = tid & 31;
    const int m0   = blockIdx.y * 128;
    const int n0   = blockIdx.x * 128;
    const int wm   = (warp >> 1) * 32;
    const int wn   = (warp & 1) * 64;
    const int tg   = lane & 3;
    const int grp  = lane >> 2;

    float acc[2][8][4];
    #pragma unroll
    for (int i = 0; i < 2; i++)
        #pragma unroll
        for (int j = 0; j < 8; j++)
            #pragma unroll
            for (int q = 0; q < 4; q++) acc[i][j][q] = 0.0f;

    float4 ra[4], rbu[2], rbw[2];

    // --- prefetch helpers (A: 128x32, B: 32x128) ---
    auto loadG = [&](int k0) {
        #pragma unroll
        for (int t = 0; t < 4; t++) {
            int idx = tid + t * 256;
            int m = idx >> 3, k4 = (idx & 7) * 4;
            ra[t] = *(const float4*)&A[(size_t)(m0 + m) * K + k0 + k4];
        }
        #pragma unroll
        for (int t = 0; t < 2; t++) {
            int idx = tid + t * 256;
            int kp = idx >> 5, n4 = (idx & 31) * 4;
            const float* Brow = &B[(size_t)(k0 + 2 * kp) * N + n0 + n4];
            rbu[t] = *(const float4*)Brow;
            rbw[t] = *(const float4*)(Brow + N);
        }
    };
    auto storeS = [&](int buf) {
        #pragma unroll
        for (int t = 0; t < 4; t++) {
            int idx = tid + t * 256;
            int m = idx >> 3, kp = (idx & 7) * 2;
            uint32_t h0, l0, h1, l1;
            split_pack2(ra[t].x, ra[t].y, h0, l0);
            split_pack2(ra[t].z, ra[t].w, h1, l1);
            AH_(buf, m, kp)     = h0;  AL_(buf, m, kp)     = l0;
            AH_(buf, m, kp + 1) = h1;  AL_(buf, m, kp + 1) = l1;
        }
        #pragma unroll
        for (int t = 0; t < 2; t++) {
            int idx = tid + t * 256;
            int kp = idx >> 5, n4 = (idx & 31) * 4;
            uint32_t h, l;
            split_pack2(rbu[t].x, rbw[t].x, h, l); BH_(buf, n4+0, kp) = h; BL_(buf, n4+0, kp) = l;
            split_pack2(rbu[t].y, rbw[t].y, h, l); BH_(buf, n4+1, kp) = h; BL_(buf, n4+1, kp) = l;
            split_pack2(rbu[t].z, rbw[t].z, h, l); BH_(buf, n4+2, kp) = h; BL_(buf, n4+2, kp) = l;
            split_pack2(rbu[t].w, rbw[t].w, h, l); BH_(buf, n4+3, kp) = h; BL_(buf, n4+3, kp) = l;
        }
    };

    const int nIter = K >> 5;
    loadG(0);
    storeS(0);
    __syncthreads();

    for (int it = 0; it < nIter; it++) {
        const int cur = it & 1;
        if (it + 1 < nIter) loadG((it + 1) << 5);

        // ---- compute on buffer `cur` ----
        #pragma unroll
        for (int kc = 0; kc < 2; kc++) {
            const int c8 = kc * 8;
            uint32_t afh[2][4], afl[2][4];
            #pragma unroll
            for (int i = 0; i < 2; i++) {
                int r = wm + i * 16 + grp;
                afh[i][0] = AH_(cur, r,     c8 + tg);
                afh[i][1] = AH_(cur, r + 8, c8 + tg);
                afh[i][2] = AH_(cur, r,     c8 + 4 + tg);
                afh[i][3] = AH_(cur, r + 8, c8 + 4 + tg);
                afl[i][0] = AL_(cur, r,     c8 + tg);
                afl[i][1] = AL_(cur, r + 8, c8 + tg);
                afl[i][2] = AL_(cur, r,     c8 + 4 + tg);
                afl[i][3] = AL_(cur, r + 8, c8 + 4 + tg);
            }
            #pragma unroll
            for (int j = 0; j < 8; j++) {
                int n = wn + j * 8 + grp;
                uint32_t bh[2] = { BH_(cur, n, c8 + tg), BH_(cur, n, c8 + 4 + tg) };
                uint32_t bl[2] = { BL_(cur, n, c8 + tg), BL_(cur, n, c8 + 4 + tg) };
                #pragma unroll
                for (int i = 0; i < 2; i++) {
                    MMA_BF16(acc[i][j], afh[i], bh);
                    MMA_BF16(acc[i][j], afh[i], bl);
                    MMA_BF16(acc[i][j], afl[i], bh);
                }
            }
        }

        if (it + 1 < nIter) storeS(cur ^ 1);
        __syncthreads();
    }

    // ---- epilogue ----
    #pragma unroll
    for (int i = 0; i < 2; i++) {
        int r = m0 + wm + i * 16 + grp;
        #pragma unroll
        for (int j = 0; j < 8; j++) {
            int c = n0 + wn + j * 8 + tg * 2;
            float b0 = bias[c], b1 = bias[c + 1];
            float2 v0 = make_float2(acc[i][j][0] + b0, acc[i][j][1] + b1);
            float2 v1 = make_float2(acc[i][j][2] + b0, acc[i][j][3] + b1);
            if (relu) {
                v0.x = fmaxf(v0.x, 0.0f); v0.y = fmaxf(v0.y, 0.0f);
                v1.x = fmaxf(v1.x, 0.0f); v1.y = fmaxf(v1.y, 0.0f);
            }
            *(float2*)&C[(size_t)r * N + c]       = v0;
            *(float2*)&C[(size_t)(r + 8) * N + c] = v1;
        }
    }
}

// ---------------------------------------------------------------------------
// Tensor-core flash attention.
// Grid: (T/128, H, N). Block: 256 threads (8 warps, 16 q-rows each).
// QK^T: bf16 split (3 MMAs). Softmax in registers. P@V: plain bf16.
// Scale 1/8 folded into Q at load. Mask: query-axis -> no-op, skipped.
// ---------------------------------------------------------------------------
__global__ __launch_bounds__(256)
void attention_mma_kernel(const float* __restrict__ qkv,
                          float* __restrict__ ctx)
{
    // union region: Q staging (2*128*33 = 8448 u32), later Kh/Kl/Vp (6304 u32)
    __shared__ uint32_t smem[8448];
    uint32_t* Qh_s = smem;                 // [128][33]
    uint32_t* Ql_s = smem + 128 * 33;      // [128][33]
    uint32_t* Kh_s = smem;                 // [64][33]
    uint32_t* Kl_s = smem + 64 * 33;       // [64][33]
    uint32_t* Vp_s = smem + 128 * 33;      // [32][65]

    const int tid  = threadIdx.x;
    const int warp = tid >> 5;
    const int lane = tid & 31;
    const int tg   = lane & 3;
    const int grp  = lane >> 2;
    const int wm   = warp * 16;

    const int q0 = blockIdx.x * 128;
    const int h  = blockIdx.y;
    const int n  = blockIdx.z;
    const int h64 = h * HD;
    const size_t row_base = (size_t)n * T_SEQ;

    // ---- stage Q (x 0.125), split, pack pairs along d ----
    for (int p = tid; p < 128 * 32; p += 256) {
        int row = p >> 5, dp = p & 31;
        size_t base = (row_base + q0 + row) * QKV_N + (size_t)(h64 + dp * 2) * 3;
        float f0 = qkv[base]     * 0.125f;
        float f1 = qkv[base + 3] * 0.125f;
        uint32_t hi, lo;
        split_pack2(f0, f1, hi, lo);
        Qh_s[row * 33 + dp] = hi;
        Ql_s[row * 33 + dp] = lo;
    }
    __syncthreads();

    // ---- per-warp resident Q fragments ----
    uint32_t qh[4][4], ql[4][4];
    #pragma unroll
    for (int kc = 0; kc < 4; kc++) {
        int r = wm + grp;
        qh[kc][0] = Qh_s[r * 33 + kc * 8 + tg];
        qh[kc][1] = Qh_s[(r + 8) * 33 + kc * 8 + tg];
        qh[kc][2] = Qh_s[r * 33 + kc * 8 + 4 + tg];
        qh[kc][3] = Qh_s[(r + 8) * 33 + kc * 8 + 4 + tg];
        ql[kc][0] = Ql_s[r * 33 + kc * 8 + tg];
        ql[kc][1] = Ql_s[(r + 8) * 33 + kc * 8 + tg];
        ql[kc][2] = Ql_s[r * 33 + kc * 8 + 4 + tg];
        ql[kc][3] = Ql_s[(r + 8) * 33 + kc * 8 + 4 + tg];
    }

    float o[8][4];
    #pragma unroll
    for (int j = 0; j < 8; j++)
        #pragma unroll
        for (int q = 0; q < 4; q++) o[j][q] = 0.0f;
    float m0 = -1e30f, m1 = -1e30f, l0 = 0.0f, l1 = 0.0f;

    for (int kt = 0; kt < T_SEQ / 64; kt++) {
        const int kv0 = kt * 64;
        __syncthreads();
        // ---- load K tile (64x64), split, pairs along d ----
        for (int p = tid; p < 64 * 32; p += 256) {
            int kv = p >> 5, dp = p & 31;
            size_t base = (row_base + kv0 + kv) * QKV_N + (size_t)(h64 + dp * 2) * 3 + 1;
            uint32_t hi, lo;
            split_pack2(qkv[base], qkv[base + 3], hi, lo);
            Kh_s[kv * 33 + dp] = hi;
            Kl_s[kv * 33 + dp] = lo;
        }
        // ---- load V tile (64x64), plain bf16, pairs along kv ----
        for (int p = tid; p < 32 * 64; p += 256) {
            int kvp = p >> 6, d = p & 63;
            size_t base = (row_base + kv0 + kvp * 2) * QKV_N + (size_t)(h64 + d) * 3 + 2;
            Vp_s[kvp * 65 + d] = pack_bf16(qkv[base], qkv[base + QKV_N]);
        }
        __syncthreads();

        // ---- S = Q @ K^T ----
        float s[8][4];
        #pragma unroll
        for (int j = 0; j < 8; j++)
            #pragma unroll
            for (int q = 0; q < 4; q++) s[j][q] = 0.0f;
        #pragma unroll
        for (int j = 0; j < 8; j++) {
            int kvr = j * 8 + grp;
            #pragma unroll
            for (int kc = 0; kc < 4; kc++) {
                uint32_t bh[2] = { Kh_s[kvr * 33 + kc * 8 + tg], Kh_s[kvr * 33 + kc * 8 + 4 + tg] };
                uint32_t bl[2] = { Kl_s[kvr * 33 + kc * 8 + tg], Kl_s[kvr * 33 + kc * 8 + 4 + tg] };
                MMA_BF16(s[j], qh[kc], bh);
                MMA_BF16(s[j], qh[kc], bl);
                MMA_BF16(s[j], ql[kc], bh);
            }
        }

        // ---- online softmax (rows grp, grp+8) ----
        float mx0 = -1e30f, mx1 = -1e30f;
        #pragma unroll
        for (int j = 0; j < 8; j++) {
            mx0 = fmaxf(mx0, fmaxf(s[j][0], s[j][1]));
            mx1 = fmaxf(mx1, fmaxf(s[j][2], s[j][3]));
        }
        mx0 = fmaxf(mx0, __shfl_xor_sync(0xffffffff, mx0, 1));
        mx0 = fmaxf(mx0, __shfl_xor_sync(0xffffffff, mx0, 2));
        mx1 = fmaxf(mx1, __shfl_xor_sync(0xffffffff, mx1, 1));
        mx1 = fmaxf(mx1, __shfl_xor_sync(0xffffffff, mx1, 2));
        float mn0 = fmaxf(m0, mx0), mn1 = fmaxf(m1, mx1);
        float al0 = __expf(m0 - mn0), al1 = __expf(m1 - mn1);
        float sum0 = 0.0f, sum1 = 0.0f;
        #pragma unroll
        for (int j = 0; j < 8; j++) {
            s[j][0] = __expf(s[j][0] - mn0);
            s[j][1] = __expf(s[j][1] - mn0);
            s[j][2] = __expf(s[j][2] - mn1);
            s[j][3] = __expf(s[j][3] - mn1);
            sum0 += s[j][0] + s[j][1];
            sum1 += s[j][2] + s[j][3];
        }
        sum0 += __shfl_xor_sync(0xffffffff, sum0, 1);
        sum0 += __shfl_xor_sync(0xffffffff, sum0, 2);
        sum1 += __shfl_xor_sync(0xffffffff, sum1, 1);
        sum1 += __shfl_xor_sync(0xffffffff, sum1, 2);
        m0 = mn0; m1 = mn1;
        l0 = l0 * al0 + sum0;
        l1 = l1 * al1 + sum1;
        #pragma unroll
        for (int j = 0; j < 8; j++) {
            o[j][0] *= al0; o[j][1] *= al0;
            o[j][2] *= al1; o[j][3] *= al1;
        }

        // ---- pack P fragments, PV ----
        uint32_t ap[4][4];
        #pragma unroll
        for (int kc = 0; kc < 4; kc++) {
            ap[kc][0] = pack_bf16(s[2*kc][0],   s[2*kc][1]);
            ap[kc][1] = pack_bf16(s[2*kc][2],   s[2*kc][3]);
            ap[kc][2] = pack_bf16(s[2*kc+1][0], s[2*kc+1][1]);
            ap[kc][3] = pack_bf16(s[2*kc+1][2], s[2*kc+1][3]);
        }
        #pragma unroll
        for (int j = 0; j < 8; j++) {
            int d8 = j * 8 + grp;
            #pragma unroll
            for (int kc = 0; kc < 4; kc++) {
                uint32_t bv[2] = { Vp_s[(kc * 8 + tg) * 65 + d8],
                                   Vp_s[(kc * 8 + 4 + tg) * 65 + d8] };
                MMA_BF16(o[j], ap[kc], bv);
            }
        }
    }

    // ---- epilogue ----
    float inv0 = 1.0f / l0, inv1 = 1.0f / l1;
    size_t r0 = (row_base + q0 + wm + grp) * (size_t)DM + h64;
    size_t r1 = r0 + 8 * (size_t)DM;
    #pragma unroll
    for (int j = 0; j < 8; j++) {
        int c = j * 8 + tg * 2;
        *(float2*)&ctx[r0 + c] = make_float2(o[j][0] * inv0, o[j][1] * inv0);
        *(float2*)&ctx[r1 + c] = make_float2(o[j][2] * inv1, o[j][3] * inv1);
    }
}

// ---------------------------------------------------------------------------
// out[row] = LayerNorm(a[row] + b[row]) * gamma + beta  (D = 1024)
// ---------------------------------------------------------------------------
__global__ void add_ln_kernel(const float* __restrict__ a,
                              const float* __restrict__ b,
                              const float* __restrict__ gamma,
                              const float* __restrict__ beta,
                              float* __restrict__ out)
{
    __shared__ float red[256];
    const int row = blockIdx.x;
    const int tid = threadIdx.x;
    const size_t base = (size_t)row * DM;

    float v[4];
    float s = 0.0f;
    #pragma unroll
    for (int i = 0; i < 4; i++) {
        int c = tid + 256 * i;
        v[i] = a[base + c] + b[base + c];
        s += v[i];
    }
    red[tid] = s;
    __syncthreads();
    #pragma unroll
    for (int off = 128; off > 0; off >>= 1) {
        if (tid < off) red[tid] += red[tid + off];
        __syncthreads();
    }
    const float mu = red[0] * (1.0f / DM);
    __syncthreads();

    float s2 = 0.0f;
    #pragma unroll
    for (int i = 0; i < 4; i++) {
        float d = v[i] - mu;
        s2 += d * d;
    }
    red[tid] = s2;
    __syncthreads();
    #pragma unroll
    for (int off = 128; off > 0; off >>= 1) {
        if (tid < off) red[tid] += red[tid + off];
        __syncthreads();
    }
    const float rs = rsqrtf(red[0] * (1.0f / DM) + LN_EPS);

    #pragma unroll
    for (int i = 0; i < 4; i++) {
        int c = tid + 256 * i;
        out[base + c] = (v[i] - mu) * rs * gamma[c] + beta[c];
    }
}

// ---------------------------------------------------------------------------
// Launch
// ---------------------------------------------------------------------------
extern "C" void kernel_launch(void* const* d_in, const int* in_sizes, int n_in,
                              void* d_out, int out_size)
{
    const float* x     = (const float*)d_in[0];
    /* mask = d_in[1] : query-axis mask -> softmax shift -> no-op */
    const float* w_qkv = (const float*)d_in[2];
    const float* b_qkv = (const float*)d_in[3];
    const float* w_ff  = (const float*)d_in[4];
    const float* b_ff  = (const float*)d_in[5];
    const float* w_out = (const float*)d_in[6];
    const float* b_out = (const float*)d_in[7];
    const float* ln1_g = (const float*)d_in[8];
    const float* ln1_b = (const float*)d_in[9];
    const float* ln2_g = (const float*)d_in[10];
    const float* ln2_b = (const float*)d_in[11];
    float* out = (float*)d_out;

    float *qkv, *ctx, *h1, *ff, *tmp;
    cudaGetSymbolAddress((void**)&qkv, g_qkv);
    cudaGetSymbolAddress((void**)&ctx, g_ctx);
    cudaGetSymbolAddress((void**)&h1,  g_h1);
    cudaGetSymbolAddress((void**)&ff,  g_ff);
    cudaGetSymbolAddress((void**)&tmp, g_tmp);

    static int smem_set = 0;
    if (!smem_set) {
        cudaFuncSetAttribute(gemm_mma_kernel,
                             cudaFuncAttributeMaxDynamicSharedMemorySize,
                             GEMM_SMEM_BYTES);
        smem_set = 1;
    }

    // 1) QKV projection
    gemm_mma_kernel<<<dim3(QKV_N / 128, NT / 128), 256, GEMM_SMEM_BYTES>>>(
        x, w_qkv, b_qkv, qkv, NT, QKV_N, DM, 0);

    // 2) Attention
    attention_mma_kernel<<<dim3(T_SEQ / 128, H_NUM, NB), 256>>>(qkv, ctx);

    // 3) h1 = LN(x + ctx)
    add_ln_kernel<<<NT, 256>>>(x, ctx, ln1_g, ln1_b, h1);

    // 4) ff = relu(h1 @ w_ff + b_ff)
    gemm_mma_kernel<<<dim3(DFF / 128, NT / 128), 256, GEMM_SMEM_BYTES>>>(
        h1, w_ff, b_ff, ff, NT, DFF, DM, 1);

    // 5) tmp = ff @ w_out + b_out
    gemm_mma_kernel<<<dim3(DM / 128, NT / 128), 256, GEMM_SMEM_BYTES>>>(
        ff, w_out, b_out, tmp, NT, DM, DFF, 0);

    // 6) out = LN(h1 + tmp)
    add_ln_kernel<<<NT, 256>>>(h1, tmp, ln2_g, ln2_b, out);
}

// round 4
// speedup vs baseline: 3.6907x; 1.1961x over previous
#include <cuda_runtime.h>
#include <cuda_bf16.h>
#include <math.h>
#include <stdint.h>

// ---------------------------------------------------------------------------
// Problem constants
// ---------------------------------------------------------------------------
#define NB      2
#define T_SEQ   2048
#define NT      (NB * T_SEQ)        // 4096 tokens
#define DM      1024
#define H_NUM   16
#define HD      64
#define DFF     4096
#define QKV_N   (3 * DM)            // 3072
#define LN_EPS  1e-3f

// ---------------------------------------------------------------------------
// Scratch
// ---------------------------------------------------------------------------
__device__ float g_qkv[NT * QKV_N];                 // 50 MB
__device__ float g_ctx[NT * DM];                    // 16 MB
__device__ float g_h1 [NT * DM];                    // 16 MB
__device__ float g_tmp[NT * DM];                    // 16 MB
__device__ __nv_bfloat16 g_ahi[NT * DM];            // A-side hi (x, then h1)
__device__ __nv_bfloat16 g_alo[NT * DM];
__device__ __nv_bfloat16 g_bhi[4 * 1024 * 1024];    // transposed weights hi
__device__ __nv_bfloat16 g_blo[4 * 1024 * 1024];
__device__ __nv_bfloat16 g_ffhi[NT * DFF];          // ff hi (written by FFN1)
__device__ __nv_bfloat16 g_fflo[NT * DFF];

// ---------------------------------------------------------------------------
// Helpers
// ---------------------------------------------------------------------------
__device__ __forceinline__ void split_pack2(float x, float y,
                                            uint32_t& hi, uint32_t& lo)
{
    __nv_bfloat16 hx = __float2bfloat16(x);
    __nv_bfloat16 hy = __float2bfloat16(y);
    __nv_bfloat16 lx = __float2bfloat16(x - __bfloat162float(hx));
    __nv_bfloat16 ly = __float2bfloat16(y - __bfloat162float(hy));
    hi = (uint32_t)__bfloat16_as_ushort(hx) |
         ((uint32_t)__bfloat16_as_ushort(hy) << 16);
    lo = (uint32_t)__bfloat16_as_ushort(lx) |
         ((uint32_t)__bfloat16_as_ushort(ly) << 16);
}

__device__ __forceinline__ uint32_t pack_bf16(float x, float y)
{
    return (uint32_t)__bfloat16_as_ushort(__float2bfloat16(x)) |
           ((uint32_t)__bfloat16_as_ushort(__float2bfloat16(y)) << 16);
}

#define MMA_BF16(d, a, b)                                                   \
    asm volatile(                                                           \
        "mma.sync.aligned.m16n8k16.row.col.f32.bf16.bf16.f32 "              \
        "{%0,%1,%2,%3}, {%4,%5,%6,%7}, {%8,%9}, {%0,%1,%2,%3};"             \
        : "+f"(d[0]), "+f"(d[1]), "+f"(d[2]), "+f"(d[3])                    \
        : "r"(a[0]), "r"(a[1]), "r"(a[2]), "r"(a[3]), "r"(b[0]), "r"(b[1]))

#define LDSM_X4(R, addr)                                                    \
    asm volatile("ldmatrix.sync.aligned.m8n8.x4.shared.b16 "                \
                 "{%0,%1,%2,%3}, [%4];"                                     \
                 : "=r"(R[0]), "=r"(R[1]), "=r"(R[2]), "=r"(R[3])           \
                 : "r"(addr))

__device__ __forceinline__ void cp16(uint32_t dst, const void* src)
{
    asm volatile("cp.async.cg.shared.global [%0], [%1], 16;"
                 :: "r"(dst), "l"(src));
}

// ---------------------------------------------------------------------------
// Conversion kernels
// ---------------------------------------------------------------------------
// fp32 [n] -> hi/lo bf16 (pairwise)
__global__ void convert_split_kernel(const float* __restrict__ in,
                                     __nv_bfloat16* __restrict__ hi,
                                     __nv_bfloat16* __restrict__ lo,
                                     int npairs)
{
    int i = blockIdx.x * blockDim.x + threadIdx.x;
    if (i >= npairs) return;
    float2 v = ((const float2*)in)[i];
    uint32_t h, l;
    split_pack2(v.x, v.y, h, l);
    ((uint32_t*)hi)[i] = h;
    ((uint32_t*)lo)[i] = l;
}

// W [Kd][Nd] fp32 -> Wt hi/lo bf16 [Nd][Kd]
__global__ void convert_wT_kernel(const float* __restrict__ W,
                                  __nv_bfloat16* __restrict__ hi,
                                  __nv_bfloat16* __restrict__ lo,
                                  int Kd, int Nd)
{
    __shared__ float t[32][33];
    const int tx = threadIdx.x, ty = threadIdx.y;
    const int n0 = blockIdx.x * 32, k0 = blockIdx.y * 32;
    #pragma unroll
    for (int r = ty; r < 32; r += 8)
        t[r][tx] = W[(size_t)(k0 + r) * Nd + n0 + tx];
    __syncthreads();
    #pragma unroll
    for (int r = ty; r < 32; r += 8) {
        float v = t[tx][r];             // W[k0+tx][n0+r]
        __nv_bfloat16 h = __float2bfloat16(v);
        hi[(size_t)(n0 + r) * Kd + k0 + tx] = h;
        lo[(size_t)(n0 + r) * Kd + k0 + tx] =
            __float2bfloat16(v - __bfloat162float(h));
    }
}

// ---------------------------------------------------------------------------
// Tensor-core GEMM, bf16x3 split, cp.async double-buffered + ldmatrix.
//   C = A @ B^T(stored [N][K]) + bias, optional ReLU.
//   Output: fp32 C, or hi/lo bf16 split pair.
// Block 128x128x32, 256 threads (8 warps 4x2), warp 32x64.
// Smem: 4 arrays x [2 bufs][128 rows][80 B] = 81920 B dynamic.
// ---------------------------------------------------------------------------
#define ROWB   80
#define ABUF   10240            // 128*80
#define OFF_AH 0
#define OFF_AL 20480
#define OFF_BH 40960
#define OFF_BL 61440
#define GEMM_SMEM_BYTES 81920

__global__ __launch_bounds__(256, 2)
void gemm_mma_kernel(const __nv_bfloat16* __restrict__ Ahi,
                     const __nv_bfloat16* __restrict__ Alo,
                     const __nv_bfloat16* __restrict__ Bhi,
                     const __nv_bfloat16* __restrict__ Blo,
                     const float* __restrict__ bias,
                     float* __restrict__ Cf,
                     __nv_bfloat16* __restrict__ Chi,
                     __nv_bfloat16* __restrict__ Clo,
                     int N, int K, int relu)
{
    extern __shared__ char smem[];
    const uint32_t sb = (uint32_t)__cvta_generic_to_shared(smem);

    const int tid  = threadIdx.x;
    const int warp = tid >> 5;
    const int lane = tid & 31;
    const int m0   = blockIdx.y * 128;
    const int n0   = blockIdx.x * 128;
    const int wm   = (warp >> 1) * 32;
    const int wn   = (warp & 1) * 64;
    const int tg   = lane & 3;
    const int grp  = lane >> 2;

    float acc[2][8][4];
    #pragma unroll
    for (int i = 0; i < 2; i++)
        #pragma unroll
        for (int j = 0; j < 8; j++)
            #pragma unroll
            for (int q = 0; q < 4; q++) acc[i][j][q] = 0.0f;

    auto issueTile = [&](int k0, int buf) {
        const uint32_t bo = buf * ABUF;
        #pragma unroll
        for (int t = 0; t < 2; t++) {
            int q   = tid + t * 256;        // 0..511
            int row = q >> 2, ch = q & 3;
            uint32_t so = bo + row * ROWB + ch * 16;
            size_t ao = (size_t)(m0 + row) * K + k0 + ch * 8;
            size_t bo2 = (size_t)(n0 + row) * K + k0 + ch * 8;
            cp16(sb + OFF_AH + so, Ahi + ao);
            cp16(sb + OFF_AL + so, Alo + ao);
            cp16(sb + OFF_BH + so, Bhi + bo2);
            cp16(sb + OFF_BL + so, Blo + bo2);
        }
    };

    auto computeTile = [&](int buf) {
        const uint32_t bo = buf * ABUF;
        const int rr = lane & 15;
        #pragma unroll
        for (int kc = 0; kc < 2; kc++) {
            const uint32_t ko = kc * 32 + ((lane >> 4) << 4);
            uint32_t ah[2][4], al[2][4];
            #pragma unroll
            for (int i = 0; i < 2; i++) {
                uint32_t ad = sb + bo + (wm + i * 16 + rr) * ROWB + ko;
                LDSM_X4(ah[i], ad + OFF_AH);
                LDSM_X4(al[i], ad + OFF_AL);
            }
            #pragma unroll
            for (int jj = 0; jj < 4; jj++) {
                uint32_t bd = sb + bo + (wn + jj * 16 + rr) * ROWB + ko;
                uint32_t bh[4], bl[4];
                LDSM_X4(bh, bd + OFF_BH);
                LDSM_X4(bl, bd + OFF_BL);
                uint32_t bh0[2] = { bh[0], bh[2] }, bh1[2] = { bh[1], bh[3] };
                uint32_t bl0[2] = { bl[0], bl[2] }, bl1[2] = { bl[1], bl[3] };
                #pragma unroll
                for (int i = 0; i < 2; i++) {
                    MMA_BF16(acc[i][2*jj],   ah[i], bh0);
                    MMA_BF16(acc[i][2*jj],   ah[i], bl0);
                    MMA_BF16(acc[i][2*jj],   al[i], bh0);
                    MMA_BF16(acc[i][2*jj+1], ah[i], bh1);
                    MMA_BF16(acc[i][2*jj+1], ah[i], bl1);
                    MMA_BF16(acc[i][2*jj+1], al[i], bh1);
                }
            }
        }
    };

    const int nIter = K >> 5;
    issueTile(0, 0);
    asm volatile("cp.async.commit_group;");

    for (int it = 0; it < nIter; it++) {
        const int buf = it & 1;
        if (it + 1 < nIter) {
            issueTile((it + 1) << 5, buf ^ 1);
            asm volatile("cp.async.commit_group;");
            asm volatile("cp.async.wait_group 1;");
        } else {
            asm volatile("cp.async.wait_group 0;");
        }
        __syncthreads();
        computeTile(buf);
        __syncthreads();
    }

    // ---- epilogue ----
    #pragma unroll
    for (int i = 0; i < 2; i++) {
        int r = m0 + wm + i * 16 + grp;
        #pragma unroll
        for (int j = 0; j < 8; j++) {
            int c = n0 + wn + j * 8 + tg * 2;
            float b0 = bias[c], b1 = bias[c + 1];
            float v0 = acc[i][j][0] + b0, v1 = acc[i][j][1] + b1;
            float v2 = acc[i][j][2] + b0, v3 = acc[i][j][3] + b1;
            if (relu) {
                v0 = fmaxf(v0, 0.0f); v1 = fmaxf(v1, 0.0f);
                v2 = fmaxf(v2, 0.0f); v3 = fmaxf(v3, 0.0f);
            }
            if (Cf) {
                *(float2*)&Cf[(size_t)r * N + c]       = make_float2(v0, v1);
                *(float2*)&Cf[(size_t)(r + 8) * N + c] = make_float2(v2, v3);
            } else {
                uint32_t h, l;
                split_pack2(v0, v1, h, l);
                *(uint32_t*)&Chi[(size_t)r * N + c] = h;
                *(uint32_t*)&Clo[(size_t)r * N + c] = l;
                split_pack2(v2, v3, h, l);
                *(uint32_t*)&Chi[(size_t)(r + 8) * N + c] = h;
                *(uint32_t*)&Clo[(size_t)(r + 8) * N + c] = l;
            }
        }
    }
}

// ---------------------------------------------------------------------------
// Tensor-core flash attention (unchanged from R2).
// ---------------------------------------------------------------------------
__global__ __launch_bounds__(256)
void attention_mma_kernel(const float* __restrict__ qkv,
                          float* __restrict__ ctx)
{
    __shared__ uint32_t smem[8448];
    uint32_t* Qh_s = smem;
    uint32_t* Ql_s = smem + 128 * 33;
    uint32_t* Kh_s = smem;
    uint32_t* Kl_s = smem + 64 * 33;
    uint32_t* Vp_s = smem + 128 * 33;

    const int tid  = threadIdx.x;
    const int warp = tid >> 5;
    const int lane = tid & 31;
    const int tg   = lane & 3;
    const int grp  = lane >> 2;
    const int wm   = warp * 16;

    const int q0 = blockIdx.x * 128;
    const int h  = blockIdx.y;
    const int n  = blockIdx.z;
    const int h64 = h * HD;
    const size_t row_base = (size_t)n * T_SEQ;

    for (int p = tid; p < 128 * 32; p += 256) {
        int row = p >> 5, dp = p & 31;
        size_t base = (row_base + q0 + row) * QKV_N + (size_t)(h64 + dp * 2) * 3;
        float f0 = qkv[base]     * 0.125f;
        float f1 = qkv[base + 3] * 0.125f;
        uint32_t hi, lo;
        split_pack2(f0, f1, hi, lo);
        Qh_s[row * 33 + dp] = hi;
        Ql_s[row * 33 + dp] = lo;
    }
    __syncthreads();

    uint32_t qh[4][4], ql[4][4];
    #pragma unroll
    for (int kc = 0; kc < 4; kc++) {
        int r = wm + grp;
        qh[kc][0] = Qh_s[r * 33 + kc * 8 + tg];
        qh[kc][1] = Qh_s[(r + 8) * 33 + kc * 8 + tg];
        qh[kc][2] = Qh_s[r * 33 + kc * 8 + 4 + tg];
        qh[kc][3] = Qh_s[(r + 8) * 33 + kc * 8 + 4 + tg];
        ql[kc][0] = Ql_s[r * 33 + kc * 8 + tg];
        ql[kc][1] = Ql_s[(r + 8) * 33 + kc * 8 + tg];
        ql[kc][2] = Ql_s[r * 33 + kc * 8 + 4 + tg];
        ql[kc][3] = Ql_s[(r + 8) * 33 + kc * 8 + 4 + tg];
    }

    float o[8][4];
    #pragma unroll
    for (int j = 0; j < 8; j++)
        #pragma unroll
        for (int q = 0; q < 4; q++) o[j][q] = 0.0f;
    float m0 = -1e30f, m1 = -1e30f, l0 = 0.0f, l1 = 0.0f;

    for (int kt = 0; kt < T_SEQ / 64; kt++) {
        const int kv0 = kt * 64;
        __syncthreads();
        for (int p = tid; p < 64 * 32; p += 256) {
            int kv = p >> 5, dp = p & 31;
            size_t base = (row_base + kv0 + kv) * QKV_N + (size_t)(h64 + dp * 2) * 3 + 1;
            uint32_t hi, lo;
            split_pack2(qkv[base], qkv[base + 3], hi, lo);
            Kh_s[kv * 33 + dp] = hi;
            Kl_s[kv * 33 + dp] = lo;
        }
        for (int p = tid; p < 32 * 64; p += 256) {
            int kvp = p >> 6, d = p & 63;
            size_t base = (row_base + kv0 + kvp * 2) * QKV_N + (size_t)(h64 + d) * 3 + 2;
            Vp_s[kvp * 65 + d] = pack_bf16(qkv[base], qkv[base + QKV_N]);
        }
        __syncthreads();

        float s[8][4];
        #pragma unroll
        for (int j = 0; j < 8; j++)
            #pragma unroll
            for (int q = 0; q < 4; q++) s[j][q] = 0.0f;
        #pragma unroll
        for (int j = 0; j < 8; j++) {
            int kvr = j * 8 + grp;
            #pragma unroll
            for (int kc = 0; kc < 4; kc++) {
                uint32_t bh[2] = { Kh_s[kvr * 33 + kc * 8 + tg], Kh_s[kvr * 33 + kc * 8 + 4 + tg] };
                uint32_t bl[2] = { Kl_s[kvr * 33 + kc * 8 + tg], Kl_s[kvr * 33 + kc * 8 + 4 + tg] };
                MMA_BF16(s[j], qh[kc], bh);
                MMA_BF16(s[j], qh[kc], bl);
                MMA_BF16(s[j], ql[kc], bh);
            }
        }

        float mx0 = -1e30f, mx1 = -1e30f;
        #pragma unroll
        for (int j = 0; j < 8; j++) {
            mx0 = fmaxf(mx0, fmaxf(s[j][0], s[j][1]));
            mx1 = fmaxf(mx1, fmaxf(s[j][2], s[j][3]));
        }
        mx0 = fmaxf(mx0, __shfl_xor_sync(0xffffffff, mx0, 1));
        mx0 = fmaxf(mx0, __shfl_xor_sync(0xffffffff, mx0, 2));
        mx1 = fmaxf(mx1, __shfl_xor_sync(0xffffffff, mx1, 1));
        mx1 = fmaxf(mx1, __shfl_xor_sync(0xffffffff, mx1, 2));
        float mn0 = fmaxf(m0, mx0), mn1 = fmaxf(m1, mx1);
        float al0 = __expf(m0 - mn0), al1 = __expf(m1 - mn1);
        float sum0 = 0.0f, sum1 = 0.0f;
        #pragma unroll
        for (int j = 0; j < 8; j++) {
            s[j][0] = __expf(s[j][0] - mn0);
            s[j][1] = __expf(s[j][1] - mn0);
            s[j][2] = __expf(s[j][2] - mn1);
            s[j][3] = __expf(s[j][3] - mn1);
            sum0 += s[j][0] + s[j][1];
            sum1 += s[j][2] + s[j][3];
        }
        sum0 += __shfl_xor_sync(0xffffffff, sum0, 1);
        sum0 += __shfl_xor_sync(0xffffffff, sum0, 2);
        sum1 += __shfl_xor_sync(0xffffffff, sum1, 1);
        sum1 += __shfl_xor_sync(0xffffffff, sum1, 2);
        m0 = mn0; m1 = mn1;
        l0 = l0 * al0 + sum0;
        l1 = l1 * al1 + sum1;
        #pragma unroll
        for (int j = 0; j < 8; j++) {
            o[j][0] *= al0; o[j][1] *= al0;
            o[j][2] *= al1; o[j][3] *= al1;
        }

        uint32_t ap[4][4];
        #pragma unroll
        for (int kc = 0; kc < 4; kc++) {
            ap[kc][0] = pack_bf16(s[2*kc][0],   s[2*kc][1]);
            ap[kc][1] = pack_bf16(s[2*kc][2],   s[2*kc][3]);
            ap[kc][2] = pack_bf16(s[2*kc+1][0], s[2*kc+1][1]);
            ap[kc][3] = pack_bf16(s[2*kc+1][2], s[2*kc+1][3]);
        }
        #pragma unroll
        for (int j = 0; j < 8; j++) {
            int d8 = j * 8 + grp;
            #pragma unroll
            for (int kc = 0; kc < 4; kc++) {
                uint32_t bv[2] = { Vp_s[(kc * 8 + tg) * 65 + d8],
                                   Vp_s[(kc * 8 + 4 + tg) * 65 + d8] };
                MMA_BF16(o[j], ap[kc], bv);
            }
        }
    }

    float inv0 = 1.0f / l0, inv1 = 1.0f / l1;
    size_t r0 = (row_base + q0 + wm + grp) * (size_t)DM + h64;
    size_t r1 = r0 + 8 * (size_t)DM;
    #pragma unroll
    for (int j = 0; j < 8; j++) {
        int c = j * 8 + tg * 2;
        *(float2*)&ctx[r0 + c] = make_float2(o[j][0] * inv0, o[j][1] * inv0);
        *(float2*)&ctx[r1 + c] = make_float2(o[j][2] * inv1, o[j][3] * inv1);
    }
}

// ---------------------------------------------------------------------------
// out = LayerNorm(a + b) * gamma + beta; optional hi/lo bf16 side outputs.
// ---------------------------------------------------------------------------
__global__ void add_ln_kernel(const float* __restrict__ a,
                              const float* __restrict__ b,
                              const float* __restrict__ gamma,
                              const float* __restrict__ beta,
                              float* __restrict__ out,
                              __nv_bfloat16* __restrict__ ohi,
                              __nv_bfloat16* __restrict__ olo)
{
    __shared__ float red[256];
    const int row = blockIdx.x;
    const int tid = threadIdx.x;
    const size_t base = (size_t)row * DM;

    float v[4];
    float s = 0.0f;
    #pragma unroll
    for (int i = 0; i < 4; i++) {
        int c = tid + 256 * i;
        v[i] = a[base + c] + b[base + c];
        s += v[i];
    }
    red[tid] = s;
    __syncthreads();
    #pragma unroll
    for (int off = 128; off > 0; off >>= 1) {
        if (tid < off) red[tid] += red[tid + off];
        __syncthreads();
    }
    const float mu = red[0] * (1.0f / DM);
    __syncthreads();

    float s2 = 0.0f;
    #pragma unroll
    for (int i = 0; i < 4; i++) {
        float d = v[i] - mu;
        s2 += d * d;
    }
    red[tid] = s2;
    __syncthreads();
    #pragma unroll
    for (int off = 128; off > 0; off >>= 1) {
        if (tid < off) red[tid] += red[tid + off];
        __syncthreads();
    }
    const float rs = rsqrtf(red[0] * (1.0f / DM) + LN_EPS);

    #pragma unroll
    for (int i = 0; i < 4; i++) {
        int c = tid + 256 * i;
        float y = (v[i] - mu) * rs * gamma[c] + beta[c];
        out[base + c] = y;
        if (ohi) {
            __nv_bfloat16 hb = __float2bfloat16(y);
            ohi[base + c] = hb;
            olo[base + c] = __float2bfloat16(y - __bfloat162float(hb));
        }
    }
}

// ---------------------------------------------------------------------------
// Launch
// ---------------------------------------------------------------------------
extern "C" void kernel_launch(void* const* d_in, const int* in_sizes, int n_in,
                              void* d_out, int out_size)
{
    const float* x     = (const float*)d_in[0];
    /* mask = d_in[1] : query-axis mask -> softmax shift -> no-op */
    const float* w_qkv = (const float*)d_in[2];
    const float* b_qkv = (const float*)d_in[3];
    const float* w_ff  = (const float*)d_in[4];
    const float* b_ff  = (const float*)d_in[5];
    const float* w_out = (const float*)d_in[6];
    const float* b_out = (const float*)d_in[7];
    const float* ln1_g = (const float*)d_in[8];
    const float* ln1_b = (const float*)d_in[9];
    const float* ln2_g = (const float*)d_in[10];
    const float* ln2_b = (const float*)d_in[11];
    float* out = (float*)d_out;

    float *qkv, *ctx, *h1, *tmp;
    __nv_bfloat16 *ahi, *alo, *bhi, *blo, *ffhi, *fflo;
    cudaGetSymbolAddress((void**)&qkv,  g_qkv);
    cudaGetSymbolAddress((void**)&ctx,  g_ctx);
    cudaGetSymbolAddress((void**)&h1,   g_h1);
    cudaGetSymbolAddress((void**)&tmp,  g_tmp);
    cudaGetSymbolAddress((void**)&ahi,  g_ahi);
    cudaGetSymbolAddress((void**)&alo,  g_alo);
    cudaGetSymbolAddress((void**)&bhi,  g_bhi);
    cudaGetSymbolAddress((void**)&blo,  g_blo);
    cudaGetSymbolAddress((void**)&ffhi, g_ffhi);
    cudaGetSymbolAddress((void**)&fflo, g_fflo);

    static int smem_set = 0;
    if (!smem_set) {
        cudaFuncSetAttribute(gemm_mma_kernel,
                             cudaFuncAttributeMaxDynamicSharedMemorySize,
                             GEMM_SMEM_BYTES);
        smem_set = 1;
    }

    // 0) Convert x -> hi/lo; w_qkv -> transposed hi/lo
    convert_split_kernel<<<(NT * DM / 2 + 255) / 256, 256>>>(x, ahi, alo, NT * DM / 2);
    convert_wT_kernel<<<dim3(QKV_N / 32, DM / 32), dim3(32, 8)>>>(w_qkv, bhi, blo, DM, QKV_N);

    // 1) QKV projection: [4096,1024] @ [1024,3072] -> fp32
    gemm_mma_kernel<<<dim3(QKV_N / 128, NT / 128), 256, GEMM_SMEM_BYTES>>>(
        ahi, alo, bhi, blo, b_qkv, qkv, nullptr, nullptr, QKV_N, DM, 0);

    // 2) Attention
    attention_mma_kernel<<<dim3(T_SEQ / 128, H_NUM, NB), 256>>>(qkv, ctx);

    // 3) h1 = LN(x + ctx), also emit h1 hi/lo into ahi/alo
    add_ln_kernel<<<NT, 256>>>(x, ctx, ln1_g, ln1_b, h1, ahi, alo);

    // 4) ff = relu(h1 @ w_ff + b_ff) -> written directly as hi/lo bf16
    convert_wT_kernel<<<dim3(DFF / 32, DM / 32), dim3(32, 8)>>>(w_ff, bhi, blo, DM, DFF);
    gemm_mma_kernel<<<dim3(DFF / 128, NT / 128), 256, GEMM_SMEM_BYTES>>>(
        ahi, alo, bhi, blo, b_ff, nullptr, ffhi, fflo, DFF, DM, 1);

    // 5) tmp = ff @ w_out + b_out -> fp32
    convert_wT_kernel<<<dim3(DM / 32, DFF / 32), dim3(32, 8)>>>(w_out, bhi, blo, DFF, DM);
    gemm_mma_kernel<<<dim3(DM / 128, NT / 128), 256, GEMM_SMEM_BYTES>>>(
        ffhi, fflo, bhi, blo, b_out, tmp, nullptr, nullptr, DM, DFF, 0);

    // 6) out = LN(h1 + tmp)
    add_ln_kernel<<<NT, 256>>>(h1, tmp, ln2_g, ln2_b, out, nullptr, nullptr);
}

// round 5
// speedup vs baseline: 4.6511x; 1.2602x over previous
#include <cuda_runtime.h>
#include <cuda_bf16.h>
#include <math.h>
#include <stdint.h>

// ---------------------------------------------------------------------------
// Problem constants
// ---------------------------------------------------------------------------
#define NB      2
#define T_SEQ   2048
#define NT      (NB * T_SEQ)        // 4096 tokens
#define DM      1024
#define H_NUM   16
#define HD      64
#define DFF     4096
#define QKV_N   (3 * DM)            // 3072
#define LN_EPS  1e-3f

// ---------------------------------------------------------------------------
// Scratch
// ---------------------------------------------------------------------------
__device__ float g_ctx[NT * DM];
__device__ float g_h1 [NT * DM];
__device__ float g_tmp[NT * DM];
__device__ __nv_bfloat16 g_ahi[NT * DM];
__device__ __nv_bfloat16 g_alo[NT * DM];
__device__ __nv_bfloat16 g_bhi[4 * 1024 * 1024];
__device__ __nv_bfloat16 g_blo[4 * 1024 * 1024];
__device__ __nv_bfloat16 g_ffhi[NT * DFF];
__device__ __nv_bfloat16 g_fflo[NT * DFF];
// attention-native QKV (bf16, layout [token][h*64+d])
__device__ __nv_bfloat16 g_qh[NT * DM];
__device__ __nv_bfloat16 g_ql[NT * DM];
__device__ __nv_bfloat16 g_kh[NT * DM];
__device__ __nv_bfloat16 g_kl[NT * DM];
__device__ __nv_bfloat16 g_vb[NT * DM];

// ---------------------------------------------------------------------------
// Helpers
// ---------------------------------------------------------------------------
__device__ __forceinline__ void split_pack2(float x, float y,
                                            uint32_t& hi, uint32_t& lo)
{
    __nv_bfloat16 hx = __float2bfloat16(x);
    __nv_bfloat16 hy = __float2bfloat16(y);
    __nv_bfloat16 lx = __float2bfloat16(x - __bfloat162float(hx));
    __nv_bfloat16 ly = __float2bfloat16(y - __bfloat162float(hy));
    hi = (uint32_t)__bfloat16_as_ushort(hx) |
         ((uint32_t)__bfloat16_as_ushort(hy) << 16);
    lo = (uint32_t)__bfloat16_as_ushort(lx) |
         ((uint32_t)__bfloat16_as_ushort(ly) << 16);
}

__device__ __forceinline__ uint32_t pack_bf16(float x, float y)
{
    return (uint32_t)__bfloat16_as_ushort(__float2bfloat16(x)) |
           ((uint32_t)__bfloat16_as_ushort(__float2bfloat16(y)) << 16);
}

#define MMA_BF16(d, a, b)                                                   \
    asm volatile(                                                           \
        "mma.sync.aligned.m16n8k16.row.col.f32.bf16.bf16.f32 "              \
        "{%0,%1,%2,%3}, {%4,%5,%6,%7}, {%8,%9}, {%0,%1,%2,%3};"             \
        : "+f"(d[0]), "+f"(d[1]), "+f"(d[2]), "+f"(d[3])                    \
        : "r"(a[0]), "r"(a[1]), "r"(a[2]), "r"(a[3]), "r"(b[0]), "r"(b[1]))

#define LDSM_X4(R, addr)                                                    \
    asm volatile("ldmatrix.sync.aligned.m8n8.x4.shared.b16 "                \
                 "{%0,%1,%2,%3}, [%4];"                                     \
                 : "=r"(R[0]), "=r"(R[1]), "=r"(R[2]), "=r"(R[3])           \
                 : "r"(addr))

#define LDSM_X4_T(R, addr)                                                  \
    asm volatile("ldmatrix.sync.aligned.m8n8.x4.trans.shared.b16 "          \
                 "{%0,%1,%2,%3}, [%4];"                                     \
                 : "=r"(R[0]), "=r"(R[1]), "=r"(R[2]), "=r"(R[3])           \
                 : "r"(addr))

__device__ __forceinline__ void cp16(uint32_t dst, const void* src)
{
    asm volatile("cp.async.cg.shared.global [%0], [%1], 16;"
                 :: "r"(dst), "l"(src));
}

// ---------------------------------------------------------------------------
// Conversion kernels
// ---------------------------------------------------------------------------
__global__ void convert_split_kernel(const float* __restrict__ in,
                                     __nv_bfloat16* __restrict__ hi,
                                     __nv_bfloat16* __restrict__ lo,
                                     int npairs)
{
    int i = blockIdx.x * blockDim.x + threadIdx.x;
    if (i >= npairs) return;
    float2 v = ((const float2*)in)[i];
    uint32_t h, l;
    split_pack2(v.x, v.y, h, l);
    ((uint32_t*)hi)[i] = h;
    ((uint32_t*)lo)[i] = l;
}

// W [Kd][Nd] fp32 -> Wt hi/lo bf16 [Nd][Kd].
// qkv_perm: dest row for src col n is (n%3)*1024 + n/3  (comp-major).
__global__ void convert_wT_kernel(const float* __restrict__ W,
                                  __nv_bfloat16* __restrict__ hi,
                                  __nv_bfloat16* __restrict__ lo,
                                  int Kd, int Nd, int qkv_perm)
{
    __shared__ float t[32][33];
    const int tx = threadIdx.x, ty = threadIdx.y;
    const int n0 = blockIdx.x * 32, k0 = blockIdx.y * 32;
    #pragma unroll
    for (int r = ty; r < 32; r += 8)
        t[r][tx] = W[(size_t)(k0 + r) * Nd + n0 + tx];
    __syncthreads();
    #pragma unroll
    for (int r = ty; r < 32; r += 8) {
        float v = t[tx][r];
        int n = n0 + r;
        int drow = qkv_perm ? ((n % 3) * 1024 + n / 3) : n;
        __nv_bfloat16 h = __float2bfloat16(v);
        hi[(size_t)drow * Kd + k0 + tx] = h;
        lo[(size_t)drow * Kd + k0 + tx] =
            __float2bfloat16(v - __bfloat162float(h));
    }
}

// ---------------------------------------------------------------------------
// Tensor-core GEMM, bf16x3 split, cp.async double-buffered + ldmatrix.
// Output modes: qkv-special (Qh!=0), fp32 (Cf!=0), or hi/lo split.
// ---------------------------------------------------------------------------
#define ROWB   80
#define ABUF   10240
#define OFF_AH 0
#define OFF_AL 20480
#define OFF_BH 40960
#define OFF_BL 61440
#define GEMM_SMEM_BYTES 81920

__global__ __launch_bounds__(256, 2)
void gemm_mma_kernel(const __nv_bfloat16* __restrict__ Ahi,
                     const __nv_bfloat16* __restrict__ Alo,
                     const __nv_bfloat16* __restrict__ Bhi,
                     const __nv_bfloat16* __restrict__ Blo,
                     const float* __restrict__ bias,
                     float* __restrict__ Cf,
                     __nv_bfloat16* __restrict__ Chi,
                     __nv_bfloat16* __restrict__ Clo,
                     __nv_bfloat16* __restrict__ Qh,
                     __nv_bfloat16* __restrict__ Ql,
                     __nv_bfloat16* __restrict__ Kh,
                     __nv_bfloat16* __restrict__ Kl,
                     __nv_bfloat16* __restrict__ Vb,
                     int N, int K, int relu)
{
    extern __shared__ char smem[];
    const uint32_t sb = (uint32_t)__cvta_generic_to_shared(smem);

    const int tid  = threadIdx.x;
    const int warp = tid >> 5;
    const int lane = tid & 31;
    const int m0   = blockIdx.y * 128;
    const int n0   = blockIdx.x * 128;
    const int wm   = (warp >> 1) * 32;
    const int wn   = (warp & 1) * 64;
    const int tg   = lane & 3;
    const int grp  = lane >> 2;

    float acc[2][8][4];
    #pragma unroll
    for (int i = 0; i < 2; i++)
        #pragma unroll
        for (int j = 0; j < 8; j++)
            #pragma unroll
            for (int q = 0; q < 4; q++) acc[i][j][q] = 0.0f;

    auto issueTile = [&](int k0, int buf) {
        const uint32_t bo = buf * ABUF;
        #pragma unroll
        for (int t = 0; t < 2; t++) {
            int q   = tid + t * 256;
            int row = q >> 2, ch = q & 3;
            uint32_t so = bo + row * ROWB + ch * 16;
            size_t ao  = (size_t)(m0 + row) * K + k0 + ch * 8;
            size_t bo2 = (size_t)(n0 + row) * K + k0 + ch * 8;
            cp16(sb + OFF_AH + so, Ahi + ao);
            cp16(sb + OFF_AL + so, Alo + ao);
            cp16(sb + OFF_BH + so, Bhi + bo2);
            cp16(sb + OFF_BL + so, Blo + bo2);
        }
    };

    auto computeTile = [&](int buf) {
        const uint32_t bo = buf * ABUF;
        const int rr = lane & 15;
        #pragma unroll
        for (int kc = 0; kc < 2; kc++) {
            const uint32_t ko = kc * 32 + ((lane >> 4) << 4);
            uint32_t ah[2][4], al[2][4];
            #pragma unroll
            for (int i = 0; i < 2; i++) {
                uint32_t ad = sb + bo + (wm + i * 16 + rr) * ROWB + ko;
                LDSM_X4(ah[i], ad + OFF_AH);
                LDSM_X4(al[i], ad + OFF_AL);
            }
            #pragma unroll
            for (int jj = 0; jj < 4; jj++) {
                uint32_t bd = sb + bo + (wn + jj * 16 + rr) * ROWB + ko;
                uint32_t bh[4], bl[4];
                LDSM_X4(bh, bd + OFF_BH);
                LDSM_X4(bl, bd + OFF_BL);
                uint32_t bh0[2] = { bh[0], bh[2] }, bh1[2] = { bh[1], bh[3] };
                uint32_t bl0[2] = { bl[0], bl[2] }, bl1[2] = { bl[1], bl[3] };
                #pragma unroll
                for (int i = 0; i < 2; i++) {
                    MMA_BF16(acc[i][2*jj],   ah[i], bh0);
                    MMA_BF16(acc[i][2*jj],   ah[i], bl0);
                    MMA_BF16(acc[i][2*jj],   al[i], bh0);
                    MMA_BF16(acc[i][2*jj+1], ah[i], bh1);
                    MMA_BF16(acc[i][2*jj+1], ah[i], bl1);
                    MMA_BF16(acc[i][2*jj+1], al[i], bh1);
                }
            }
        }
    };

    const int nIter = K >> 5;
    issueTile(0, 0);
    asm volatile("cp.async.commit_group;");

    for (int it = 0; it < nIter; it++) {
        const int buf = it & 1;
        if (it + 1 < nIter) {
            issueTile((it + 1) << 5, buf ^ 1);
            asm volatile("cp.async.commit_group;");
            asm volatile("cp.async.wait_group 1;");
        } else {
            asm volatile("cp.async.wait_group 0;");
        }
        __syncthreads();
        computeTile(buf);
        __syncthreads();
    }

    // ---- epilogue ----
    #pragma unroll
    for (int i = 0; i < 2; i++) {
        int r = m0 + wm + i * 16 + grp;
        #pragma unroll
        for (int j = 0; j < 8; j++) {
            int c = n0 + wn + j * 8 + tg * 2;
            if (Qh) {
                // qkv mode: c is comp-major permuted column; bias at orig col
                int comp = c >> 10, cd = c & 1023;
                float b0 = bias[cd * 3 + comp], b1 = bias[(cd + 1) * 3 + comp];
                float v0 = acc[i][j][0] + b0, v1 = acc[i][j][1] + b1;
                float v2 = acc[i][j][2] + b0, v3 = acc[i][j][3] + b1;
                size_t o0 = (size_t)r * DM + cd;
                size_t o1 = (size_t)(r + 8) * DM + cd;
                uint32_t h, l;
                if (comp == 0) {
                    split_pack2(v0 * 0.125f, v1 * 0.125f, h, l);
                    *(uint32_t*)&Qh[o0] = h; *(uint32_t*)&Ql[o0] = l;
                    split_pack2(v2 * 0.125f, v3 * 0.125f, h, l);
                    *(uint32_t*)&Qh[o1] = h; *(uint32_t*)&Ql[o1] = l;
                } else if (comp == 1) {
                    split_pack2(v0, v1, h, l);
                    *(uint32_t*)&Kh[o0] = h; *(uint32_t*)&Kl[o0] = l;
                    split_pack2(v2, v3, h, l);
                    *(uint32_t*)&Kh[o1] = h; *(uint32_t*)&Kl[o1] = l;
                } else {
                    *(uint32_t*)&Vb[o0] = pack_bf16(v0, v1);
                    *(uint32_t*)&Vb[o1] = pack_bf16(v2, v3);
                }
            } else {
                float b0 = bias[c], b1 = bias[c + 1];
                float v0 = acc[i][j][0] + b0, v1 = acc[i][j][1] + b1;
                float v2 = acc[i][j][2] + b0, v3 = acc[i][j][3] + b1;
                if (relu) {
                    v0 = fmaxf(v0, 0.0f); v1 = fmaxf(v1, 0.0f);
                    v2 = fmaxf(v2, 0.0f); v3 = fmaxf(v3, 0.0f);
                }
                if (Cf) {
                    *(float2*)&Cf[(size_t)r * N + c]       = make_float2(v0, v1);
                    *(float2*)&Cf[(size_t)(r + 8) * N + c] = make_float2(v2, v3);
                } else {
                    uint32_t h, l;
                    split_pack2(v0, v1, h, l);
                    *(uint32_t*)&Chi[(size_t)r * N + c] = h;
                    *(uint32_t*)&Clo[(size_t)r * N + c] = l;
                    split_pack2(v2, v3, h, l);
                    *(uint32_t*)&Chi[(size_t)(r + 8) * N + c] = h;
                    *(uint32_t*)&Clo[(size_t)(r + 8) * N + c] = l;
                }
            }
        }
    }
}

// ---------------------------------------------------------------------------
// Tensor-core flash attention, cp.async + ldmatrix, double-buffered KV.
// Grid (T/128, H, N), 256 threads. Q scale pre-folded. ctx fp32 out.
// ---------------------------------------------------------------------------
#define ATT_SROW 144
#define ATT_KBUF 27648          // per buf: Kh 9216 | Kl 9216 | V 9216
#define ATT_SMEM 55296

__global__ __launch_bounds__(256, 2)
void attention_mma_kernel(const __nv_bfloat16* __restrict__ Qh,
                          const __nv_bfloat16* __restrict__ Ql,
                          const __nv_bfloat16* __restrict__ Kh,
                          const __nv_bfloat16* __restrict__ Kl,
                          const __nv_bfloat16* __restrict__ Vb,
                          float* __restrict__ ctx)
{
    extern __shared__ char smem[];
    const uint32_t sb = (uint32_t)__cvta_generic_to_shared(smem);

    const int tid  = threadIdx.x;
    const int warp = tid >> 5;
    const int lane = tid & 31;
    const int tg   = lane & 3;
    const int grp  = lane >> 2;
    const int wm   = warp * 16;
    const int rr   = lane & 15;
    const int kb   = (lane >> 4) << 4;

    const int q0 = blockIdx.x * 128;
    const int h  = blockIdx.y;
    const int n  = blockIdx.z;
    const int h64 = h * HD;
    const size_t row_base = (size_t)n * T_SEQ;

    // ---- stage Q (hi at 0, lo at 18432), extract resident fragments ----
    #pragma unroll
    for (int t = 0; t < 4; t++) {
        int u = tid + t * 256;          // 0..1023
        int row = u >> 3, ch = u & 7;
        size_t g = (size_t)(row_base + q0 + row) * DM + h64 + ch * 8;
        uint32_t so = row * ATT_SROW + ch * 16;
        cp16(sb + so, Qh + g);
        cp16(sb + 18432 + so, Ql + g);
    }
    asm volatile("cp.async.commit_group;");
    asm volatile("cp.async.wait_group 0;");
    __syncthreads();

    uint32_t qfh[4][4], qfl[4][4];
    #pragma unroll
    for (int kc = 0; kc < 4; kc++) {
        uint32_t ad = sb + (wm + rr) * ATT_SROW + kc * 32 + kb;
        LDSM_X4(qfh[kc], ad);
        LDSM_X4(qfl[kc], ad + 18432);
    }
    __syncthreads();   // everyone done with Q region before KV overwrites it

    auto issueKV = [&](int kt, int buf) {
        uint32_t bo = sb + buf * ATT_KBUF;
        int kv0 = kt * 64;
        #pragma unroll
        for (int t = 0; t < 2; t++) {
            int u = tid + t * 256;      // 0..511
            int row = u >> 3, ch = u & 7;
            size_t g = (size_t)(row_base + kv0 + row) * DM + h64 + ch * 8;
            uint32_t so = row * ATT_SROW + ch * 16;
            cp16(bo + so,         Kh + g);
            cp16(bo + 9216 + so,  Kl + g);
            cp16(bo + 18432 + so, Vb + g);
        }
    };

    float o[8][4];
    #pragma unroll
    for (int j = 0; j < 8; j++)
        #pragma unroll
        for (int q = 0; q < 4; q++) o[j][q] = 0.0f;
    float m0 = -1e30f, m1 = -1e30f, l0 = 0.0f, l1 = 0.0f;

    const int nTiles = T_SEQ / 64;
    issueKV(0, 0);
    asm volatile("cp.async.commit_group;");

    for (int kt = 0; kt < nTiles; kt++) {
        const int buf = kt & 1;
        if (kt + 1 < nTiles) {
            issueKV(kt + 1, buf ^ 1);
            asm volatile("cp.async.commit_group;");
            asm volatile("cp.async.wait_group 1;");
        } else {
            asm volatile("cp.async.wait_group 0;");
        }
        __syncthreads();

        const uint32_t bo = sb + buf * ATT_KBUF;

        // ---- S = Q @ K^T ----
        float s[8][4];
        #pragma unroll
        for (int j = 0; j < 8; j++)
            #pragma unroll
            for (int q = 0; q < 4; q++) s[j][q] = 0.0f;
        #pragma unroll
        for (int jj = 0; jj < 4; jj++) {
            #pragma unroll
            for (int kc = 0; kc < 4; kc++) {
                uint32_t ad = bo + (jj * 16 + rr) * ATT_SROW + kc * 32 + kb;
                uint32_t bh[4], bl[4];
                LDSM_X4(bh, ad);
                LDSM_X4(bl, ad + 9216);
                uint32_t bh0[2] = { bh[0], bh[2] }, bh1[2] = { bh[1], bh[3] };
                uint32_t bl0[2] = { bl[0], bl[2] }, bl1[2] = { bl[1], bl[3] };
                MMA_BF16(s[2*jj],   qfh[kc], bh0);
                MMA_BF16(s[2*jj],   qfh[kc], bl0);
                MMA_BF16(s[2*jj],   qfl[kc], bh0);
                MMA_BF16(s[2*jj+1], qfh[kc], bh1);
                MMA_BF16(s[2*jj+1], qfh[kc], bl1);
                MMA_BF16(s[2*jj+1], qfl[kc], bh1);
            }
        }

        // ---- online softmax ----
        float mx0 = -1e30f, mx1 = -1e30f;
        #pragma unroll
        for (int j = 0; j < 8; j++) {
            mx0 = fmaxf(mx0, fmaxf(s[j][0], s[j][1]));
            mx1 = fmaxf(mx1, fmaxf(s[j][2], s[j][3]));
        }
        mx0 = fmaxf(mx0, __shfl_xor_sync(0xffffffff, mx0, 1));
        mx0 = fmaxf(mx0, __shfl_xor_sync(0xffffffff, mx0, 2));
        mx1 = fmaxf(mx1, __shfl_xor_sync(0xffffffff, mx1, 1));
        mx1 = fmaxf(mx1, __shfl_xor_sync(0xffffffff, mx1, 2));
        float mn0 = fmaxf(m0, mx0), mn1 = fmaxf(m1, mx1);
        float al0 = __expf(m0 - mn0), al1 = __expf(m1 - mn1);
        float sum0 = 0.0f, sum1 = 0.0f;
        #pragma unroll
        for (int j = 0; j < 8; j++) {
            s[j][0] = __expf(s[j][0] - mn0);
            s[j][1] = __expf(s[j][1] - mn0);
            s[j][2] = __expf(s[j][2] - mn1);
            s[j][3] = __expf(s[j][3] - mn1);
            sum0 += s[j][0] + s[j][1];
            sum1 += s[j][2] + s[j][3];
        }
        sum0 += __shfl_xor_sync(0xffffffff, sum0, 1);
        sum0 += __shfl_xor_sync(0xffffffff, sum0, 2);
        sum1 += __shfl_xor_sync(0xffffffff, sum1, 1);
        sum1 += __shfl_xor_sync(0xffffffff, sum1, 2);
        m0 = mn0; m1 = mn1;
        l0 = l0 * al0 + sum0;
        l1 = l1 * al1 + sum1;
        #pragma unroll
        for (int j = 0; j < 8; j++) {
            o[j][0] *= al0; o[j][1] *= al0;
            o[j][2] *= al1; o[j][3] *= al1;
        }

        // ---- P fragments + PV (V via ldmatrix.trans) ----
        uint32_t ap[4][4];
        #pragma unroll
        for (int kc = 0; kc < 4; kc++) {
            ap[kc][0] = pack_bf16(s[2*kc][0],   s[2*kc][1]);
            ap[kc][1] = pack_bf16(s[2*kc][2],   s[2*kc][3]);
            ap[kc][2] = pack_bf16(s[2*kc+1][0], s[2*kc+1][1]);
            ap[kc][3] = pack_bf16(s[2*kc+1][2], s[2*kc+1][3]);
        }
        const uint32_t vrow = ((lane >> 4) << 3) + (lane & 7);
        const uint32_t vcol = ((lane >> 3) & 1) << 3;
        #pragma unroll
        for (int jd = 0; jd < 4; jd++) {
            #pragma unroll
            for (int kc = 0; kc < 4; kc++) {
                uint32_t va = bo + 18432 + (kc * 16 + vrow) * ATT_SROW
                            + (jd * 16 + vcol) * 2;
                uint32_t vr[4];
                LDSM_X4_T(vr, va);
                uint32_t vg0[2] = { vr[0], vr[2] }, vg1[2] = { vr[1], vr[3] };
                MMA_BF16(o[2*jd],   ap[kc], vg0);
                MMA_BF16(o[2*jd+1], ap[kc], vg1);
            }
        }
        __syncthreads();
    }

    // ---- epilogue ----
    float inv0 = 1.0f / l0, inv1 = 1.0f / l1;
    size_t r0 = (row_base + q0 + wm + grp) * (size_t)DM + h64;
    size_t r1 = r0 + 8 * (size_t)DM;
    #pragma unroll
    for (int j = 0; j < 8; j++) {
        int c = j * 8 + tg * 2;
        *(float2*)&ctx[r0 + c] = make_float2(o[j][0] * inv0, o[j][1] * inv0);
        *(float2*)&ctx[r1 + c] = make_float2(o[j][2] * inv1, o[j][3] * inv1);
    }
}

// ---------------------------------------------------------------------------
// out = LayerNorm(a + b) * gamma + beta; optional hi/lo bf16 side outputs.
// ---------------------------------------------------------------------------
__global__ void add_ln_kernel(const float* __restrict__ a,
                              const float* __restrict__ b,
                              const float* __restrict__ gamma,
                              const float* __restrict__ beta,
                              float* __restrict__ out,
                              __nv_bfloat16* __restrict__ ohi,
                              __nv_bfloat16* __restrict__ olo)
{
    __shared__ float red[256];
    const int row = blockIdx.x;
    const int tid = threadIdx.x;
    const size_t base = (size_t)row * DM;

    float v[4];
    float s = 0.0f;
    #pragma unroll
    for (int i = 0; i < 4; i++) {
        int c = tid + 256 * i;
        v[i] = a[base + c] + b[base + c];
        s += v[i];
    }
    red[tid] = s;
    __syncthreads();
    #pragma unroll
    for (int off = 128; off > 0; off >>= 1) {
        if (tid < off) red[tid] += red[tid + off];
        __syncthreads();
    }
    const float mu = red[0] * (1.0f / DM);
    __syncthreads();

    float s2 = 0.0f;
    #pragma unroll
    for (int i = 0; i < 4; i++) {
        float d = v[i] - mu;
        s2 += d * d;
    }
    red[tid] = s2;
    __syncthreads();
    #pragma unroll
    for (int off = 128; off > 0; off >>= 1) {
        if (tid < off) red[tid] += red[tid + off];
        __syncthreads();
    }
    const float rs = rsqrtf(red[0] * (1.0f / DM) + LN_EPS);

    #pragma unroll
    for (int i = 0; i < 4; i++) {
        int c = tid + 256 * i;
        float y = (v[i] - mu) * rs * gamma[c] + beta[c];
        out[base + c] = y;
        if (ohi) {
            __nv_bfloat16 hb = __float2bfloat16(y);
            ohi[base + c] = hb;
            olo[base + c] = __float2bfloat16(y - __bfloat162float(hb));
        }
    }
}

// ---------------------------------------------------------------------------
// Launch
// ---------------------------------------------------------------------------
extern "C" void kernel_launch(void* const* d_in, const int* in_sizes, int n_in,
                              void* d_out, int out_size)
{
    const float* x     = (const float*)d_in[0];
    /* mask = d_in[1] : query-axis mask -> softmax shift -> no-op */
    const float* w_qkv = (const float*)d_in[2];
    const float* b_qkv = (const float*)d_in[3];
    const float* w_ff  = (const float*)d_in[4];
    const float* b_ff  = (const float*)d_in[5];
    const float* w_out = (const float*)d_in[6];
    const float* b_out = (const float*)d_in[7];
    const float* ln1_g = (const float*)d_in[8];
    const float* ln1_b = (const float*)d_in[9];
    const float* ln2_g = (const float*)d_in[10];
    const float* ln2_b = (const float*)d_in[11];
    float* out = (float*)d_out;

    float *ctx, *h1, *tmp;
    __nv_bfloat16 *ahi, *alo, *bhi, *blo, *ffhi, *fflo;
    __nv_bfloat16 *qh, *ql, *kh, *kl, *vb;
    cudaGetSymbolAddress((void**)&ctx,  g_ctx);
    cudaGetSymbolAddress((void**)&h1,   g_h1);
    cudaGetSymbolAddress((void**)&tmp,  g_tmp);
    cudaGetSymbolAddress((void**)&ahi,  g_ahi);
    cudaGetSymbolAddress((void**)&alo,  g_alo);
    cudaGetSymbolAddress((void**)&bhi,  g_bhi);
    cudaGetSymbolAddress((void**)&blo,  g_blo);
    cudaGetSymbolAddress((void**)&ffhi, g_ffhi);
    cudaGetSymbolAddress((void**)&fflo, g_fflo);
    cudaGetSymbolAddress((void**)&qh,   g_qh);
    cudaGetSymbolAddress((void**)&ql,   g_ql);
    cudaGetSymbolAddress((void**)&kh,   g_kh);
    cudaGetSymbolAddress((void**)&kl,   g_kl);
    cudaGetSymbolAddress((void**)&vb,   g_vb);

    static int smem_set = 0;
    if (!smem_set) {
        cudaFuncSetAttribute(gemm_mma_kernel,
                             cudaFuncAttributeMaxDynamicSharedMemorySize,
                             GEMM_SMEM_BYTES);
        cudaFuncSetAttribute(attention_mma_kernel,
                             cudaFuncAttributeMaxDynamicSharedMemorySize,
                             ATT_SMEM);
        smem_set = 1;
    }

    // 0) Convert x -> hi/lo; w_qkv -> transposed+permuted hi/lo
    convert_split_kernel<<<(NT * DM / 2 + 255) / 256, 256>>>(x, ahi, alo, NT * DM / 2);
    convert_wT_kernel<<<dim3(QKV_N / 32, DM / 32), dim3(32, 8)>>>(w_qkv, bhi, blo, DM, QKV_N, 1);

    // 1) QKV projection -> attention-native bf16 Q/K/V
    gemm_mma_kernel<<<dim3(QKV_N / 128, NT / 128), 256, GEMM_SMEM_BYTES>>>(
        ahi, alo, bhi, blo, b_qkv, nullptr, nullptr, nullptr,
        qh, ql, kh, kl, vb, QKV_N, DM, 0);

    // 2) Attention
    attention_mma_kernel<<<dim3(T_SEQ / 128, H_NUM, NB), 256, ATT_SMEM>>>(
        qh, ql, kh, kl, vb, ctx);

    // 3) h1 = LN(x + ctx), emit h1 hi/lo
    add_ln_kernel<<<NT, 256>>>(x, ctx, ln1_g, ln1_b, h1, ahi, alo);

    // 4) ff = relu(h1 @ w_ff + b_ff) -> hi/lo bf16
    convert_wT_kernel<<<dim3(DFF / 32, DM / 32), dim3(32, 8)>>>(w_ff, bhi, blo, DM, DFF, 0);
    gemm_mma_kernel<<<dim3(DFF / 128, NT / 128), 256, GEMM_SMEM_BYTES>>>(
        ahi, alo, bhi, blo, b_ff, nullptr, ffhi, fflo,
        nullptr, nullptr, nullptr, nullptr, nullptr, DFF, DM, 1);

    // 5) tmp = ff @ w_out + b_out -> fp32
    convert_wT_kernel<<<dim3(DM / 32, DFF / 32), dim3(32, 8)>>>(w_out, bhi, blo, DFF, DM, 0);
    gemm_mma_kernel<<<dim3(DM / 128, NT / 128), 256, GEMM_SMEM_BYTES>>>(
        ffhi, fflo, bhi, blo, b_out, tmp, nullptr, nullptr,
        nullptr, nullptr, nullptr, nullptr, nullptr, DM, DFF, 0);

    // 6) out = LN(h1 + tmp)
    add_ln_kernel<<<NT, 256>>>(h1, tmp, ln2_g, ln2_b, out, nullptr, nullptr);
}